// round 1
// baseline (speedup 1.0000x reference)
#include <cuda_runtime.h>

#define HID 128
#define INP 320
#define CH  448
#define BATCH 8
#define IH 64
#define IW 128

#define TH 4
#define TW 32
#define KC 16
#define NK (CH / KC)   // 28 chunks

// ---------------- device scratch (no allocations allowed) ----------------
__device__ float g_qwd[3][CH * 9];        // quantized depthwise weights
__device__ float g_qwpT[3][CH * HID];     // quantized pointwise weights, transposed [k][o]
__device__ float g_Z [BATCH * HID * IH * IW];   // sigmoid z
__device__ float g_RH[BATCH * HID * IH * IW];   // r * h

// ---------------- weight fake-quantization ----------------
__global__ void quant_dw_kernel(const float* __restrict__ w, int g) {
    __shared__ float red[256];
    const int tid = threadIdx.x;
    const int n = CH * 9;
    float m = 0.f;
    for (int i = tid; i < n; i += 256) m = fmaxf(m, fabsf(w[i]));
    red[tid] = m; __syncthreads();
    for (int s = 128; s > 0; s >>= 1) {
        if (tid < s) red[tid] = fmaxf(red[tid], red[tid + s]);
        __syncthreads();
    }
    const float scale = fmaxf(red[0], 1e-8f) / 127.f;
    for (int i = tid; i < n; i += 256) {
        float q = rintf(w[i] / scale);          // round-half-to-even, matches jnp.round
        q = fminf(fmaxf(q, -128.f), 127.f);
        g_qwd[g][i] = q * scale;
    }
}

__global__ void quant_pw_kernel(const float* __restrict__ w, int g) {
    __shared__ float red[256];
    const int tid = threadIdx.x;
    const int n = HID * CH;                     // layout [O][K]
    float m = 0.f;
    for (int i = tid; i < n; i += 256) m = fmaxf(m, fabsf(w[i]));
    red[tid] = m; __syncthreads();
    for (int s = 128; s > 0; s >>= 1) {
        if (tid < s) red[tid] = fmaxf(red[tid], red[tid + s]);
        __syncthreads();
    }
    const float scale = fmaxf(red[0], 1e-8f) / 127.f;
    for (int i = tid; i < n; i += 256) {
        float q = rintf(w[i] / scale);
        q = fminf(fmaxf(q, -128.f), 127.f);
        int o = i / CH, k = i - o * CH;
        g_qwpT[g][k * HID + o] = q * scale;     // transpose for coalesced GEMM loads
    }
}

// ---------------- fused depthwise+pointwise gate compute ----------------
struct Smem {
    float in_s[KC][6][35];     // halo tile, padded row (35) to dodge bank conflicts
    float dw_s[KC][TH * TW];   // depthwise output [k][pixel]
    float w_s [KC][64];        // pointwise weights for this out-half [k][o]
    float wd_s[KC][9];
    float bd_s[KC];
};

__device__ __forceinline__ void gate_compute(
    Smem& s,
    const float* __restrict__ src0,   // first HID channels (h or r*h)
    const float* __restrict__ srcx,   // next INP channels (x)
    const float* __restrict__ wd,     // [CH*9] quantized
    const float* __restrict__ bd,     // [CH]
    const float* __restrict__ wpT,    // [CH*HID] quantized, transposed
    int b, int y0, int x0, int half,
    float acc[4][8])
{
    const int tid = threadIdx.x;
    const int og = tid & 15;          // output-channel group (4 ch each)
    const int pg = tid >> 4;          // pixel group (8 px each)

    #pragma unroll
    for (int i = 0; i < 4; i++)
        #pragma unroll
        for (int j = 0; j < 8; j++) acc[i][j] = 0.f;

    for (int kc = 0; kc < NK; kc++) {
        const int c0 = kc * KC;

        // ---- load input halo tile (zero-padded SAME boundary) ----
        for (int i = tid; i < KC * 6 * 34; i += 256) {
            int c   = i / 204;
            int rem = i - c * 204;
            int yy  = rem / 34;
            int xx  = rem - yy * 34;
            int gy = y0 - 1 + yy, gx = x0 - 1 + xx;
            float v = 0.f;
            if ((unsigned)gy < IH && (unsigned)gx < IW) {
                int gc = c0 + c;
                v = (gc < HID)
                    ? src0[((b * HID + gc) * IH + gy) * IW + gx]
                    : srcx[((b * INP + (gc - HID)) * IH + gy) * IW + gx];
            }
            s.in_s[c][yy][xx] = v;
        }
        // ---- load weights for this chunk ----
        for (int i = tid; i < KC * 9; i += 256) s.wd_s[i / 9][i % 9] = wd[c0 * 9 + i];
        if (tid < KC) s.bd_s[tid] = bd[c0 + tid];
        for (int i = tid; i < KC * 64; i += 256) {
            int k = i >> 6, o = i & 63;
            s.w_s[k][o] = wpT[(c0 + k) * HID + half * 64 + o];
        }
        __syncthreads();

        // ---- depthwise 3x3 into smem ----
        for (int i = tid; i < KC * (TH * TW); i += 256) {
            int c = i >> 7, p = i & 127;
            int py = p >> 5, px = p & 31;
            float a = s.bd_s[c];
            #pragma unroll
            for (int dy = 0; dy < 3; dy++)
                #pragma unroll
                for (int dx = 0; dx < 3; dx++)
                    a = fmaf(s.wd_s[c][dy * 3 + dx], s.in_s[c][py + dy][px + dx], a);
            s.dw_s[c][p] = a;
        }
        __syncthreads();

        // ---- pointwise GEMM micro-kernel: 4 outc x 8 px per thread ----
        #pragma unroll
        for (int k = 0; k < KC; k++) {
            float4 wv = *(const float4*)&s.w_s[k][og * 4];
            float4 d0 = *(const float4*)&s.dw_s[k][pg * 8];
            float4 d1 = *(const float4*)&s.dw_s[k][pg * 8 + 4];
            float wr[4] = {wv.x, wv.y, wv.z, wv.w};
            float dr[8] = {d0.x, d0.y, d0.z, d0.w, d1.x, d1.y, d1.z, d1.w};
            #pragma unroll
            for (int i = 0; i < 4; i++)
                #pragma unroll
                for (int j = 0; j < 8; j++)
                    acc[i][j] = fmaf(wr[i], dr[j], acc[i][j]);
        }
        __syncthreads();
    }
}

// ---------------- z/r kernel: writes Z and R*h scratch ----------------
__global__ void __launch_bounds__(256) zr_kernel(
    const float* __restrict__ h, const float* __restrict__ x,
    const float* __restrict__ bdz, const float* __restrict__ bdr,
    const float* __restrict__ bpz, const float* __restrict__ bpr)
{
    __shared__ Smem s;
    const int tile = blockIdx.x, half = blockIdx.y, gate = blockIdx.z; // gate 0=z, 1=r
    const int b = tile >> 6, tt = tile & 63;
    const int y0 = (tt >> 2) * TH, x0 = (tt & 3) * TW;

    const float* bd  = gate ? bdr : bdz;
    const float* bp  = gate ? bpr : bpz;
    const float* wd  = g_qwd[gate];
    const float* wpT = g_qwpT[gate];

    float acc[4][8];
    gate_compute(s, h, x, wd, bd, wpT, b, y0, x0, half, acc);

    const int og = threadIdx.x & 15, pg = threadIdx.x >> 4;
    const int p0 = pg * 8;
    const int y = y0 + (p0 >> 5), xg = x0 + (p0 & 31);
    float* dstbuf = gate ? g_RH : g_Z;

    #pragma unroll
    for (int i = 0; i < 4; i++) {
        const int oc = half * 64 + og * 4 + i;
        const float bias = bp[oc];
        const int idx0 = ((b * HID + oc) * IH + y) * IW + xg;
        float v[8];
        #pragma unroll
        for (int j = 0; j < 8; j++) {
            float sg = 1.f / (1.f + __expf(-(acc[i][j] + bias)));
            v[j] = gate ? sg * h[idx0 + j] : sg;
        }
        float4* dst = (float4*)(dstbuf + idx0);
        dst[0] = make_float4(v[0], v[1], v[2], v[3]);
        dst[1] = make_float4(v[4], v[5], v[6], v[7]);
    }
}

// ---------------- q kernel + final blend ----------------
__global__ void __launch_bounds__(256) q_kernel(
    const float* __restrict__ h, const float* __restrict__ x,
    const float* __restrict__ bdq, const float* __restrict__ bpq,
    float* __restrict__ out)
{
    __shared__ Smem s;
    const int tile = blockIdx.x, half = blockIdx.y;
    const int b = tile >> 6, tt = tile & 63;
    const int y0 = (tt >> 2) * TH, x0 = (tt & 3) * TW;

    float acc[4][8];
    gate_compute(s, g_RH, x, g_qwd[2], bdq, g_qwpT[2], b, y0, x0, half, acc);

    const int og = threadIdx.x & 15, pg = threadIdx.x >> 4;
    const int p0 = pg * 8;
    const int y = y0 + (p0 >> 5), xg = x0 + (p0 & 31);

    #pragma unroll
    for (int i = 0; i < 4; i++) {
        const int oc = half * 64 + og * 4 + i;
        const float bias = bpq[oc];
        const int idx0 = ((b * HID + oc) * IH + y) * IW + xg;
        float v[8];
        #pragma unroll
        for (int j = 0; j < 8; j++) {
            float q = tanhf(acc[i][j] + bias);
            float z = g_Z[idx0 + j];
            float hv = h[idx0 + j];
            v[j] = (1.f - z) * hv + z * q;
        }
        float4* dst = (float4*)(out + idx0);
        dst[0] = make_float4(v[0], v[1], v[2], v[3]);
        dst[1] = make_float4(v[4], v[5], v[6], v[7]);
    }
}

// ---------------- launch ----------------
extern "C" void kernel_launch(void* const* d_in, const int* in_sizes, int n_in,
                              void* d_out, int out_size) {
    const float* h   = (const float*)d_in[0];
    const float* x   = (const float*)d_in[1];
    const float* wdz = (const float*)d_in[2];
    const float* bdz = (const float*)d_in[3];
    const float* wpz = (const float*)d_in[4];
    const float* bpz = (const float*)d_in[5];
    const float* wdr = (const float*)d_in[6];
    const float* bdr = (const float*)d_in[7];
    const float* wpr = (const float*)d_in[8];
    const float* bpr = (const float*)d_in[9];
    const float* wdq = (const float*)d_in[10];
    const float* bdq = (const float*)d_in[11];
    const float* wpq = (const float*)d_in[12];
    const float* bpq = (const float*)d_in[13];
    float* out = (float*)d_out;

    quant_dw_kernel<<<1, 256>>>(wdz, 0);
    quant_dw_kernel<<<1, 256>>>(wdr, 1);
    quant_dw_kernel<<<1, 256>>>(wdq, 2);
    quant_pw_kernel<<<1, 256>>>(wpz, 0);
    quant_pw_kernel<<<1, 256>>>(wpr, 1);
    quant_pw_kernel<<<1, 256>>>(wpq, 2);

    dim3 gzr(BATCH * 64, 2, 2);   // 512 tiles x 2 out-halves x {z, r}
    zr_kernel<<<gzr, 256>>>(h, x, bdz, bdr, bpz, bpr);

    dim3 gq(BATCH * 64, 2, 1);
    q_kernel<<<gq, 256>>>(h, x, bdq, bpq, out);
}

// round 2
// speedup vs baseline: 1.3938x; 1.3938x over previous
#include <cuda_runtime.h>

#define HID 128
#define INP 320
#define CH  448
#define BATCH 8
#define IH 64
#define IW 128

#define TH 4
#define TW 32
#define KC 16
#define NK (CH / KC)   // 28 chunks

typedef unsigned long long ull;

// ---------------- device scratch ----------------
__device__ float g_qwd[3][CH * 9];        // quantized depthwise weights
__device__ float g_qwpT[3][CH * HID];     // quantized pointwise weights, transposed [k][o]
__device__ float g_Z [BATCH * HID * IH * IW];
__device__ float g_RH[BATCH * HID * IH * IW];
__device__ unsigned g_amax[6];

// ---------------- packed f32x2 helpers ----------------
__device__ __forceinline__ ull pack2(float x, float y) {
    ull r; asm("mov.b64 %0,{%1,%2};" : "=l"(r) : "f"(x), "f"(y)); return r;
}
__device__ __forceinline__ void unpack2(ull v, float& lo, float& hi) {
    asm("mov.b64 {%0,%1},%2;" : "=f"(lo), "=f"(hi) : "l"(v));
}
__device__ __forceinline__ ull ffma2(ull a, ull b, ull c) {
    ull d; asm("fma.rn.f32x2 %0, %1, %2, %3;" : "=l"(d) : "l"(a), "l"(b), "l"(c)); return d;
}

// ---------------- fake-quant prep (parallel) ----------------
__global__ void amax_init_kernel() {
    if (threadIdx.x < 6) g_amax[threadIdx.x] = 0u;
}
__global__ void amax_kernel(const float* __restrict__ w, int n, int slot) {
    float m = 0.f;
    for (int i = blockIdx.x * blockDim.x + threadIdx.x; i < n; i += gridDim.x * blockDim.x)
        m = fmaxf(m, fabsf(w[i]));
    #pragma unroll
    for (int o = 16; o; o >>= 1) m = fmaxf(m, __shfl_xor_sync(0xffffffffu, m, o));
    if ((threadIdx.x & 31) == 0) atomicMax(&g_amax[slot], __float_as_uint(m));
}
__global__ void quant_dw_kernel(const float* __restrict__ w, int g, int slot) {
    const float scale = fmaxf(__uint_as_float(g_amax[slot]), 1e-8f) / 127.f;
    int i = blockIdx.x * 256 + threadIdx.x;
    if (i < CH * 9) {
        float q = rintf(w[i] / scale);
        q = fminf(fmaxf(q, -128.f), 127.f);
        g_qwd[g][i] = q * scale;
    }
}
__global__ void quant_pw_kernel(const float* __restrict__ w, int g, int slot) {
    const float scale = fmaxf(__uint_as_float(g_amax[slot]), 1e-8f) / 127.f;
    int i = blockIdx.x * 256 + threadIdx.x;
    if (i < HID * CH) {
        float q = rintf(w[i] / scale);
        q = fminf(fmaxf(q, -128.f), 127.f);
        int o = i / CH, k = i - o * CH;
        g_qwpT[g][k * HID + o] = q * scale;   // transpose for coalesced GEMM loads
    }
}

// ---------------- fused depthwise+pointwise gate compute ----------------
struct __align__(16) Smem {
    float in_s[KC][6][35];     // halo tile (padded row)
    float dw_s[KC][TH * TW];   // depthwise output [k][pixel]
    float w_s [KC][HID];       // pointwise weights [k][o], all 128 outc
    float wd_s[KC][9];
    float bd_s[KC];
};

// acc2: 4 outc x 8 pixel-pairs (16 px) per thread, packed f32x2
__device__ __forceinline__ void gate_compute(
    Smem& s,
    const float* __restrict__ src0,   // first HID channels (h or r*h)
    const float* __restrict__ srcx,   // next INP channels (x)
    const float* __restrict__ wd, const float* __restrict__ bd,
    const float* __restrict__ wpT,
    int b, int y0, int x0,
    ull acc2[4][8])
{
    const int tid = threadIdx.x;
    const int og = tid & 31;          // 32 groups x 4 outc = 128
    const int pg = tid >> 5;          // 8 groups x 16 px = 128
    const int p0 = pg * 16;

    #pragma unroll
    for (int i = 0; i < 4; i++)
        #pragma unroll
        for (int j = 0; j < 8; j++) acc2[i][j] = 0ull;

    for (int kc = 0; kc < NK; kc++) {
        const int c0 = kc * KC;

        // ---- halo tile load (zero-padded SAME) ----
        for (int i = tid; i < KC * 6 * 34; i += 256) {
            int c   = i / 204;
            int rem = i - c * 204;
            int yy  = rem / 34;
            int xx  = rem - yy * 34;
            int gy = y0 - 1 + yy, gx = x0 - 1 + xx;
            float v = 0.f;
            if ((unsigned)gy < IH && (unsigned)gx < IW) {
                int gc = c0 + c;
                v = (gc < HID)
                    ? src0[((b * HID + gc) * IH + gy) * IW + gx]
                    : srcx[((b * INP + (gc - HID)) * IH + gy) * IW + gx];
            }
            s.in_s[c][yy][xx] = v;
        }
        for (int i = tid; i < KC * 9; i += 256) s.wd_s[i / 9][i % 9] = wd[c0 * 9 + i];
        if (tid < KC) s.bd_s[tid] = bd[c0 + tid];
        for (int i = tid; i < KC * HID; i += 256) {
            int k = i >> 7, o = i & 127;
            s.w_s[k][o] = wpT[(c0 + k) * HID + o];
        }
        __syncthreads();

        // ---- depthwise 3x3 ----
        for (int i = tid; i < KC * (TH * TW); i += 256) {
            int c = i >> 7, p = i & 127;
            int py = p >> 5, px = p & 31;
            float a = s.bd_s[c];
            #pragma unroll
            for (int dy = 0; dy < 3; dy++)
                #pragma unroll
                for (int dx = 0; dx < 3; dx++)
                    a = fmaf(s.wd_s[c][dy * 3 + dx], s.in_s[c][py + dy][px + dx], a);
            s.dw_s[c][p] = a;
        }
        __syncthreads();

        // ---- pointwise GEMM, packed f32x2: 4 outc x 8 px-pairs ----
        #pragma unroll
        for (int k = 0; k < KC; k++) {
            float4 wv = *(const float4*)&s.w_s[k][og * 4];
            ull wp[4] = { pack2(wv.x, wv.x), pack2(wv.y, wv.y),
                          pack2(wv.z, wv.z), pack2(wv.w, wv.w) };
            const ull* dp = (const ull*)&s.dw_s[k][p0];
            ull d[8];
            #pragma unroll
            for (int j = 0; j < 8; j++) d[j] = dp[j];
            #pragma unroll
            for (int i = 0; i < 4; i++)
                #pragma unroll
                for (int j = 0; j < 8; j++)
                    acc2[i][j] = ffma2(d[j], wp[i], acc2[i][j]);
        }
        __syncthreads();
    }
}

// ---------------- z/r kernel ----------------
__global__ void __launch_bounds__(256, 2) zr_kernel(
    const float* __restrict__ h, const float* __restrict__ x,
    const float* __restrict__ bdz, const float* __restrict__ bdr,
    const float* __restrict__ bpz, const float* __restrict__ bpr)
{
    __shared__ Smem s;
    const int tile = blockIdx.x, gate = blockIdx.y;   // 0=z, 1=r
    const int b = tile >> 6, tt = tile & 63;
    const int y0 = (tt >> 2) * TH, x0 = (tt & 3) * TW;

    ull acc2[4][8];
    gate_compute(s, h, x, g_qwd[gate], gate ? bdr : bdz, g_qwpT[gate], b, y0, x0, acc2);

    const int og = threadIdx.x & 31, pg = threadIdx.x >> 5;
    const int p0 = pg * 16;
    const int y = y0 + (p0 >> 5), xg = x0 + (p0 & 31);
    const float* bp = gate ? bpr : bpz;
    float* dstbuf = gate ? g_RH : g_Z;

    #pragma unroll
    for (int i = 0; i < 4; i++) {
        const int oc = og * 4 + i;
        const float bias = bp[oc];
        const int idx0 = ((b * HID + oc) * IH + y) * IW + xg;
        float v[16];
        #pragma unroll
        for (int j = 0; j < 8; j++) {
            float lo, hi; unpack2(acc2[i][j], lo, hi);
            v[2 * j]     = lo;
            v[2 * j + 1] = hi;
        }
        #pragma unroll
        for (int j = 0; j < 16; j++) {
            float sg = 1.f / (1.f + __expf(-(v[j] + bias)));
            v[j] = gate ? sg * h[idx0 + j] : sg;
        }
        float4* dst = (float4*)(dstbuf + idx0);
        #pragma unroll
        for (int j = 0; j < 4; j++)
            dst[j] = make_float4(v[4 * j], v[4 * j + 1], v[4 * j + 2], v[4 * j + 3]);
    }
}

// ---------------- q kernel + final blend ----------------
__global__ void __launch_bounds__(256, 2) q_kernel(
    const float* __restrict__ h, const float* __restrict__ x,
    const float* __restrict__ bdq, const float* __restrict__ bpq,
    float* __restrict__ out)
{
    __shared__ Smem s;
    const int tile = blockIdx.x;
    const int b = tile >> 6, tt = tile & 63;
    const int y0 = (tt >> 2) * TH, x0 = (tt & 3) * TW;

    ull acc2[4][8];
    gate_compute(s, g_RH, x, g_qwd[2], bdq, g_qwpT[2], b, y0, x0, acc2);

    const int og = threadIdx.x & 31, pg = threadIdx.x >> 5;
    const int p0 = pg * 16;
    const int y = y0 + (p0 >> 5), xg = x0 + (p0 & 31);

    #pragma unroll
    for (int i = 0; i < 4; i++) {
        const int oc = og * 4 + i;
        const float bias = bpq[oc];
        const int idx0 = ((b * HID + oc) * IH + y) * IW + xg;
        float v[16];
        #pragma unroll
        for (int j = 0; j < 8; j++) {
            float lo, hi; unpack2(acc2[i][j], lo, hi);
            v[2 * j]     = lo;
            v[2 * j + 1] = hi;
        }
        #pragma unroll
        for (int j = 0; j < 16; j++) {
            float q = tanhf(v[j] + bias);
            float z = g_Z[idx0 + j];
            float hv = h[idx0 + j];
            v[j] = (1.f - z) * hv + z * q;
        }
        float4* dst = (float4*)(out + idx0);
        #pragma unroll
        for (int j = 0; j < 4; j++)
            dst[j] = make_float4(v[4 * j], v[4 * j + 1], v[4 * j + 2], v[4 * j + 3]);
    }
}

// ---------------- launch ----------------
extern "C" void kernel_launch(void* const* d_in, const int* in_sizes, int n_in,
                              void* d_out, int out_size) {
    const float* h   = (const float*)d_in[0];
    const float* x   = (const float*)d_in[1];
    const float* wdz = (const float*)d_in[2];
    const float* bdz = (const float*)d_in[3];
    const float* wpz = (const float*)d_in[4];
    const float* bpz = (const float*)d_in[5];
    const float* wdr = (const float*)d_in[6];
    const float* bdr = (const float*)d_in[7];
    const float* wpr = (const float*)d_in[8];
    const float* bpr = (const float*)d_in[9];
    const float* wdq = (const float*)d_in[10];
    const float* bdq = (const float*)d_in[11];
    const float* wpq = (const float*)d_in[12];
    const float* bpq = (const float*)d_in[13];
    float* out = (float*)d_out;

    amax_init_kernel<<<1, 32>>>();
    amax_kernel<<<8,  256>>>(wdz, CH * 9, 0);
    amax_kernel<<<8,  256>>>(wdr, CH * 9, 1);
    amax_kernel<<<8,  256>>>(wdq, CH * 9, 2);
    amax_kernel<<<56, 256>>>(wpz, HID * CH, 3);
    amax_kernel<<<56, 256>>>(wpr, HID * CH, 4);
    amax_kernel<<<56, 256>>>(wpq, HID * CH, 5);

    quant_dw_kernel<<<(CH * 9 + 255) / 256, 256>>>(wdz, 0, 0);
    quant_dw_kernel<<<(CH * 9 + 255) / 256, 256>>>(wdr, 1, 1);
    quant_dw_kernel<<<(CH * 9 + 255) / 256, 256>>>(wdq, 2, 2);
    quant_pw_kernel<<<(HID * CH + 255) / 256, 256>>>(wpz, 0, 3);
    quant_pw_kernel<<<(HID * CH + 255) / 256, 256>>>(wpr, 1, 4);
    quant_pw_kernel<<<(HID * CH + 255) / 256, 256>>>(wpq, 2, 5);

    dim3 gzr(BATCH * 64, 2);   // 512 tiles x {z, r}
    zr_kernel<<<gzr, 256>>>(h, x, bdz, bdr, bpz, bpr);

    q_kernel<<<BATCH * 64, 256>>>(h, x, bdq, bpq, out);
}

// round 9
// speedup vs baseline: 2.0426x; 1.4655x over previous
#include <cuda_runtime.h>
#include <cuda_fp16.h>

#define HID 128
#define INP 320
#define CH  448
#define BATCH 8
#define IH 64
#define IW 128

#define KCM 64     // K per chunk
#define NKC 7      // 448/64
#define KSUB 16    // dw sub-chunk channels

typedef unsigned int u32;

// ---------------- device scratch ----------------
__device__ float g_qwd[3][CH * 9];                        // dequantized dw weights
__device__ __align__(16) __half g_wpA[3][NKC][128 * KCM]; // pw weights as exact ints in fp16, [kc][o][kk]
__device__ float g_Z [BATCH * HID * IH * IW];
__device__ float g_RH[BATCH * HID * IH * IW];
__device__ float g_amaxf[6];

// ---------------- PTX helpers (base sm_103-safe: ldmatrix + mma.sync) ----------------
__device__ __forceinline__ u32 smem_u32(const void* p) {
    u32 a;
    asm("{ .reg .u64 t; cvta.to.shared.u64 t, %1; cvt.u32.u64 %0, t; }" : "=r"(a) : "l"(p));
    return a;
}

__device__ __forceinline__ void ldm4(u32& r0, u32& r1, u32& r2, u32& r3, u32 addr) {
    asm volatile("ldmatrix.sync.aligned.m8n8.x4.shared.b16 {%0,%1,%2,%3}, [%4];"
                 : "=r"(r0), "=r"(r1), "=r"(r2), "=r"(r3) : "r"(addr));
}

__device__ __forceinline__ void mma16816(float* d, const u32* a, u32 b0, u32 b1) {
    asm volatile("mma.sync.aligned.m16n8k16.row.col.f32.f16.f16.f32 "
                 "{%0,%1,%2,%3},{%4,%5,%6,%7},{%8,%9},{%0,%1,%2,%3};"
                 : "+f"(d[0]), "+f"(d[1]), "+f"(d[2]), "+f"(d[3])
                 : "r"(a[0]), "r"(a[1]), "r"(a[2]), "r"(a[3]), "r"(b0), "r"(b1));
}

// ---------------- prep kernels ----------------
__global__ void amax_dw_kernel(const float* w0, const float* w1, const float* w2) {
    __shared__ float red[256];
    const float* w = blockIdx.x == 0 ? w0 : (blockIdx.x == 1 ? w1 : w2);
    float m = 0.f;
    for (int i = threadIdx.x; i < CH * 9; i += 256) m = fmaxf(m, fabsf(w[i]));
    red[threadIdx.x] = m; __syncthreads();
    for (int s = 128; s > 0; s >>= 1) {
        if (threadIdx.x < s) red[threadIdx.x] = fmaxf(red[threadIdx.x], red[threadIdx.x + s]);
        __syncthreads();
    }
    if (threadIdx.x == 0) g_amaxf[blockIdx.x] = red[0];
}
__global__ void amax_pw_kernel(const float* w0, const float* w1, const float* w2) {
    __shared__ float red[256];
    const float* w = blockIdx.x == 0 ? w0 : (blockIdx.x == 1 ? w1 : w2);
    float m = 0.f;
    for (int i = threadIdx.x; i < HID * CH; i += 256) m = fmaxf(m, fabsf(w[i]));
    red[threadIdx.x] = m; __syncthreads();
    for (int s = 128; s > 0; s >>= 1) {
        if (threadIdx.x < s) red[threadIdx.x] = fmaxf(red[threadIdx.x], red[threadIdx.x + s]);
        __syncthreads();
    }
    if (threadIdx.x == 0) g_amaxf[3 + blockIdx.x] = red[0];
}
__global__ void quant_dw_kernel(const float* w0, const float* w1, const float* w2) {
    const int g = blockIdx.y;
    const float* w = g == 0 ? w0 : (g == 1 ? w1 : w2);
    const float scale = fmaxf(g_amaxf[g], 1e-8f) / 127.f;
    int i = blockIdx.x * 256 + threadIdx.x;
    if (i < CH * 9) {
        float q = rintf(w[i] / scale);
        q = fminf(fmaxf(q, -128.f), 127.f);
        g_qwd[g][i] = q * scale;
    }
}
__global__ void quant_pw_kernel(const float* w0, const float* w1, const float* w2) {
    const int g = blockIdx.y;
    const float* w = g == 0 ? w0 : (g == 1 ? w1 : w2);
    const float scale = fmaxf(g_amaxf[3 + g], 1e-8f) / 127.f;
    int i = blockIdx.x * 256 + threadIdx.x;
    if (i < HID * CH) {
        float q = rintf(w[i] / scale);
        q = fminf(fmaxf(q, -128.f), 127.f);
        int o = i / CH, k = i - o * CH;
        g_wpA[g][k >> 6][o * 64 + (k & 63)] = __float2half_rn(q);   // exact integer in fp16
    }
}

// ---------------- fused mainloop: halo -> dw (fp32) -> fp16 B -> ldmatrix/mma.sync ----------------
// smem (bytes):
//   OFF_IN = 0      : float in_s[6*34*18]              (14688)
//   OFF_WD = 14720  : float wd[NG][64*9]
//   OFF_BD = +NG*2304: float bd[NG][64]
//   OFF_A  = +NG*256 : half A[NG][128][72]  (row stride 144 B, conflict-free ldmatrix)
//   OFF_B  = +NG*18432: half B[NG][128][72]
// NT = 256*NG threads. Warp tile: 32 outc x 64 px, acc[2 m-tiles][8 n-tiles][4].
template<int NG>
__device__ __forceinline__ void mainloop(
    char* sm,
    const float* __restrict__ src0, const float* __restrict__ srcx,
    const float* __restrict__ bdA, const float* __restrict__ bdB,
    int gate0, int b, int y0, int x0, float acc[2][8][4])
{
    constexpr int NT    = 256 * NG;
    constexpr int OFF_WD = 14720;
    constexpr int OFF_BD = OFF_WD + NG * 2304;
    constexpr int OFF_A  = OFF_BD + NG * 256;
    constexpr int ASZ    = 128 * 144;
    constexpr int OFF_B  = OFF_A + NG * ASZ;
    constexpr int PXT    = NT / 8;          // px per dw pass
    constexpr int NPASS  = 128 / PXT;

    float* in_s = (float*)sm;
    const int tid = threadIdx.x;
    const int wid = tid >> 5, lane = tid & 31;

    const int g   = (NG == 2) ? (wid >> 3) : 0;
    const int w   = (NG == 2) ? (wid & 7) : wid;
    const int ogB = (w & 3) * 32;
    const int pgB = (w >> 2) * 64;

    #pragma unroll
    for (int mi = 0; mi < 2; mi++)
        #pragma unroll
        for (int nj = 0; nj < 8; nj++)
            #pragma unroll
            for (int e = 0; e < 4; e++) acc[mi][nj][e] = 0.f;

    const u32 smbase = smem_u32(sm);
    // ldmatrix per-lane address offsets
    const u32 aOff = (u32)((lane & 15) * 144 + ((lane >> 4) << 4));
    const u32 bOff = (u32)(((lane & 7) + ((lane >> 4) << 3)) * 144 + (((lane >> 3) & 1) << 4));
    const u32 aBase = smbase + OFF_A + g * ASZ + ogB * 144 + aOff;
    const u32 bBase = smbase + OFF_B + g * ASZ + pgB * 144 + bOff;

    for (int kc = 0; kc < NKC; kc++) {
        for (int sub = 0; sub < 4; sub++) {
            __syncthreads();   // in_s reusable; prev-chunk MMA done before overwriting A/B
            const int c0 = kc * KCM + sub * KSUB;
            // halo load (zero-padded SAME)
            for (int i = tid; i < KSUB * 204; i += NT) {
                int c = i / 204, rem = i - c * 204;
                int yy = rem / 34, xx = rem - yy * 34;
                int gy = y0 - 1 + yy, gx = x0 - 1 + xx;
                float v = 0.f;
                if ((unsigned)gy < IH && (unsigned)gx < IW) {
                    int gc = c0 + c;
                    v = (gc < HID)
                        ? src0[((b * HID + gc) * IH + gy) * IW + gx]
                        : srcx[((b * INP + (gc - HID)) * IH + gy) * IW + gx];
                }
                in_s[(yy * 34 + xx) * 18 + c] = v;
            }
            if (sub == 0) {
                // stage A (scatter into stride-144 rows), dw weights, dw bias
                #pragma unroll
                for (int g2 = 0; g2 < NG; g2++) {
                    const int4* srcA = (const int4*)&g_wpA[gate0 + g2][kc][0];
                    for (int j = tid; j < 1024; j += NT) {
                        int o = j >> 3, c16 = j & 7;
                        *(int4*)(sm + OFF_A + g2 * ASZ + o * 144 + c16 * 16) = srcA[j];
                    }
                    float* wds = (float*)(sm + OFF_WD + g2 * 2304);
                    for (int i = tid; i < KCM * 9; i += NT) wds[i] = g_qwd[gate0 + g2][kc * KCM * 9 + i];
                    float* bds = (float*)(sm + OFF_BD + g2 * 256);
                    if (tid < KCM) bds[tid] = (g2 == 0 ? bdA : bdB)[kc * KCM + tid];
                }
            }
            __syncthreads();
            // depthwise: thread owns channel pair (2*pair, 2*pair+1)
            const int pair = tid & 7;
            const int kk = sub * KSUB + 2 * pair;
            float wr[NG][2][9], bb[NG][2];
            #pragma unroll
            for (int g2 = 0; g2 < NG; g2++) {
                const float* wds = (const float*)(sm + OFF_WD + g2 * 2304);
                const float* bds = (const float*)(sm + OFF_BD + g2 * 256);
                #pragma unroll
                for (int c2 = 0; c2 < 2; c2++) {
                    #pragma unroll
                    for (int j = 0; j < 9; j++) wr[g2][c2][j] = wds[(kk + c2) * 9 + j];
                    bb[g2][c2] = bds[kk + c2];
                }
            }
            #pragma unroll
            for (int pp = 0; pp < NPASS; pp++) {
                const int px = pp * PXT + (tid >> 3);
                const int ry = px >> 5, cx = px & 31;
                float a2[NG][2];
                #pragma unroll
                for (int g2 = 0; g2 < NG; g2++) { a2[g2][0] = bb[g2][0]; a2[g2][1] = bb[g2][1]; }
                #pragma unroll
                for (int dy = 0; dy < 3; dy++)
                    #pragma unroll
                    for (int dx = 0; dx < 3; dx++) {
                        const float2 v = *(const float2*)(in_s + ((ry + dy) * 34 + (cx + dx)) * 18 + 2 * pair);
                        #pragma unroll
                        for (int g2 = 0; g2 < NG; g2++) {
                            a2[g2][0] = fmaf(wr[g2][0][dy * 3 + dx], v.x, a2[g2][0]);
                            a2[g2][1] = fmaf(wr[g2][1][dy * 3 + dx], v.y, a2[g2][1]);
                        }
                    }
                #pragma unroll
                for (int g2 = 0; g2 < NG; g2++)
                    *(__half2*)(sm + OFF_B + g2 * ASZ + px * 144 + kk * 2) =
                        __floats2half2_rn(a2[g2][0], a2[g2][1]);
            }
        }
        __syncthreads();   // B complete for this chunk
        // MMA: 4 k-steps of 16
        #pragma unroll
        for (int ks = 0; ks < 4; ks++) {
            u32 af0[4], af1[4];
            ldm4(af0[0], af0[1], af0[2], af0[3], aBase + ks * 32);
            ldm4(af1[0], af1[1], af1[2], af1[3], aBase + 16 * 144 + ks * 32);
            #pragma unroll
            for (int p = 0; p < 4; p++) {
                u32 r0, r1, r2, r3;
                ldm4(r0, r1, r2, r3, bBase + p * 16 * 144 + ks * 32);
                mma16816(acc[0][2 * p],     af0, r0, r1);
                mma16816(acc[0][2 * p + 1], af0, r2, r3);
                mma16816(acc[1][2 * p],     af1, r0, r1);
                mma16816(acc[1][2 * p + 1], af1, r2, r3);
            }
        }
    }
}

// ---------------- zr kernel: z and r fused (shared halo), writes g_Z and g_RH ----------------
__global__ void __launch_bounds__(512) zr_kernel(
    const float* __restrict__ h, const float* __restrict__ x,
    const float* __restrict__ bdz, const float* __restrict__ bdr,
    const float* __restrict__ bpz, const float* __restrict__ bpr)
{
    extern __shared__ char sm[];
    const int b = blockIdx.x >> 6, tt = blockIdx.x & 63;
    const int y0 = (tt >> 2) * 4, x0 = (tt & 3) * 32;

    float acc[2][8][4];
    mainloop<2>(sm, h, x, bdz, bdr, 0, b, y0, x0, acc);

    const int wid = threadIdx.x >> 5, lane = threadIdx.x & 31;
    const int g = wid >> 3, w = wid & 7;
    const int ogB = (w & 3) * 32, pgB = (w >> 2) * 64;
    const float sc = fmaxf(g_amaxf[3 + g], 1e-8f) / 127.f;
    const float* bp = g ? bpr : bpz;
    const int r4 = lane >> 2, cp = (lane & 3) * 2;

    #pragma unroll
    for (int mi = 0; mi < 2; mi++)
        #pragma unroll
        for (int hh = 0; hh < 2; hh++) {
            const int oc = ogB + mi * 16 + r4 + hh * 8;
            const float bias = bp[oc];
            #pragma unroll
            for (int nj = 0; nj < 8; nj++) {
                const int px = pgB + nj * 8 + cp;
                const int dst = ((b * HID + oc) * IH + y0 + (px >> 5)) * IW + x0 + (px & 31);
                float v0 = acc[mi][nj][hh * 2]     * sc + bias;
                float v1 = acc[mi][nj][hh * 2 + 1] * sc + bias;
                v0 = 1.f / (1.f + __expf(-v0));
                v1 = 1.f / (1.f + __expf(-v1));
                if (g == 0) {
                    *(float2*)(g_Z + dst) = make_float2(v0, v1);
                } else {
                    const float2 hv = *(const float2*)(h + dst);
                    *(float2*)(g_RH + dst) = make_float2(v0 * hv.x, v1 * hv.y);
                }
            }
        }
}

// ---------------- q kernel + final blend ----------------
__global__ void __launch_bounds__(256) q_kernel(
    const float* __restrict__ h, const float* __restrict__ x,
    const float* __restrict__ bdq, const float* __restrict__ bpq,
    float* __restrict__ out)
{
    extern __shared__ char sm[];
    const int b = blockIdx.x >> 6, tt = blockIdx.x & 63;
    const int y0 = (tt >> 2) * 4, x0 = (tt & 3) * 32;

    float acc[2][8][4];
    mainloop<1>(sm, g_RH, x, bdq, bdq, 2, b, y0, x0, acc);

    const int wid = threadIdx.x >> 5, lane = threadIdx.x & 31;
    const int ogB = (wid & 3) * 32, pgB = (wid >> 2) * 64;
    const float sc = fmaxf(g_amaxf[5], 1e-8f) / 127.f;
    const int r4 = lane >> 2, cp = (lane & 3) * 2;

    #pragma unroll
    for (int mi = 0; mi < 2; mi++)
        #pragma unroll
        for (int hh = 0; hh < 2; hh++) {
            const int oc = ogB + mi * 16 + r4 + hh * 8;
            const float bias = bpq[oc];
            #pragma unroll
            for (int nj = 0; nj < 8; nj++) {
                const int px = pgB + nj * 8 + cp;
                const int dst = ((b * HID + oc) * IH + y0 + (px >> 5)) * IW + x0 + (px & 31);
                float q0 = tanhf(acc[mi][nj][hh * 2]     * sc + bias);
                float q1 = tanhf(acc[mi][nj][hh * 2 + 1] * sc + bias);
                const float2 zv = *(const float2*)(g_Z + dst);
                const float2 hv = *(const float2*)(h + dst);
                *(float2*)(out + dst) = make_float2(
                    (1.f - zv.x) * hv.x + zv.x * q0,
                    (1.f - zv.y) * hv.y + zv.y * q1);
            }
        }
}

// ---------------- launch ----------------
#define SMEM_ZR (14720 + 2 * 2304 + 2 * 256 + 4 * 128 * 144)   // 93568
#define SMEM_Q  (14720 + 1 * 2304 + 1 * 256 + 2 * 128 * 144)   // 54144

extern "C" void kernel_launch(void* const* d_in, const int* in_sizes, int n_in,
                              void* d_out, int out_size) {
    const float* h   = (const float*)d_in[0];
    const float* x   = (const float*)d_in[1];
    const float* wdz = (const float*)d_in[2];
    const float* bdz = (const float*)d_in[3];
    const float* wpz = (const float*)d_in[4];
    const float* bpz = (const float*)d_in[5];
    const float* wdr = (const float*)d_in[6];
    const float* bdr = (const float*)d_in[7];
    const float* wpr = (const float*)d_in[8];
    const float* bpr = (const float*)d_in[9];
    const float* wdq = (const float*)d_in[10];
    const float* bdq = (const float*)d_in[11];
    const float* wpq = (const float*)d_in[12];
    const float* bpq = (const float*)d_in[13];
    float* out = (float*)d_out;

    cudaFuncSetAttribute(zr_kernel, cudaFuncAttributeMaxDynamicSharedMemorySize, SMEM_ZR);
    cudaFuncSetAttribute(q_kernel,  cudaFuncAttributeMaxDynamicSharedMemorySize, SMEM_Q);

    amax_dw_kernel<<<3, 256>>>(wdz, wdr, wdq);
    amax_pw_kernel<<<3, 256>>>(wpz, wpr, wpq);
    dim3 gqd((CH * 9 + 255) / 256, 3);
    quant_dw_kernel<<<gqd, 256>>>(wdz, wdr, wdq);
    dim3 gqp((HID * CH + 255) / 256, 3);
    quant_pw_kernel<<<gqp, 256>>>(wpz, wpr, wpq);

    zr_kernel<<<512, 512, SMEM_ZR>>>(h, x, bdz, bdr, bpz, bpr);   // launch 5
    q_kernel <<<512, 256, SMEM_Q >>>(h, x, bdq, bpq, out);        // launch 6
}

// round 10
// speedup vs baseline: 4.0817x; 1.9983x over previous
#include <cuda_runtime.h>
#include <cuda_fp16.h>

#define HID 128
#define INP 320
#define CH  448
#define BATCH 8
#define IH 64
#define IW 128

#define KCM 64     // K per chunk
#define NKC 7      // 448/64
#define KSUB 16    // dw sub-chunk channels

typedef unsigned int u32;

// ---------------- device scratch ----------------
__device__ float g_qwd[3][CH * 9];                        // dequantized dw weights
__device__ __align__(16) __half g_wpA[3][NKC][128 * KCM]; // pw weights as exact ints in fp16, [kc][o][kk]
__device__ float g_Z [BATCH * HID * IH * IW];
__device__ float g_RH[BATCH * HID * IH * IW];
__device__ float g_amaxf[6];

// ---------------- PTX helpers (base sm_103-safe) ----------------
__device__ __forceinline__ u32 smem_u32(const void* p) {
    u32 a;
    asm("{ .reg .u64 t; cvta.to.shared.u64 t, %1; cvt.u32.u64 %0, t; }" : "=r"(a) : "l"(p));
    return a;
}
__device__ __forceinline__ void ldm4(u32& r0, u32& r1, u32& r2, u32& r3, u32 addr) {
    asm volatile("ldmatrix.sync.aligned.m8n8.x4.shared.b16 {%0,%1,%2,%3}, [%4];"
                 : "=r"(r0), "=r"(r1), "=r"(r2), "=r"(r3) : "r"(addr));
}
__device__ __forceinline__ void mma16816(float* d, const u32* a, u32 b0, u32 b1) {
    asm volatile("mma.sync.aligned.m16n8k16.row.col.f32.f16.f16.f32 "
                 "{%0,%1,%2,%3},{%4,%5,%6,%7},{%8,%9},{%0,%1,%2,%3};"
                 : "+f"(d[0]), "+f"(d[1]), "+f"(d[2]), "+f"(d[3])
                 : "r"(a[0]), "r"(a[1]), "r"(a[2]), "r"(a[3]), "r"(b0), "r"(b1));
}
__device__ __forceinline__ void cpa4(u32 dst, const void* src, bool v) {
    asm volatile("cp.async.ca.shared.global [%0], [%1], 4, %2;"
                 :: "r"(dst), "l"(src), "r"(v ? 4u : 0u) : "memory");
}
__device__ __forceinline__ void cpa16(u32 dst, const void* src) {
    asm volatile("cp.async.cg.shared.global [%0], [%1], 16;"
                 :: "r"(dst), "l"(src) : "memory");
}
#define CP_COMMIT() asm volatile("cp.async.commit_group;" ::: "memory")
#define CP_WAIT0()  asm volatile("cp.async.wait_group 0;" ::: "memory")

// ---------------- prep kernels ----------------
__global__ void amax_all_kernel(const float* wdz, const float* wdr, const float* wdq,
                                const float* wpz, const float* wpr, const float* wpq) {
    __shared__ float red[256];
    const float* ws[6] = {wdz, wdr, wdq, wpz, wpr, wpq};
    const int n = blockIdx.x < 3 ? CH * 9 : HID * CH;
    const float* w = ws[blockIdx.x];
    float m = 0.f;
    for (int i = threadIdx.x; i < n; i += 256) m = fmaxf(m, fabsf(w[i]));
    red[threadIdx.x] = m; __syncthreads();
    for (int s = 128; s > 0; s >>= 1) {
        if (threadIdx.x < s) red[threadIdx.x] = fmaxf(red[threadIdx.x], red[threadIdx.x + s]);
        __syncthreads();
    }
    if (threadIdx.x == 0) g_amaxf[blockIdx.x] = red[0];
}
__global__ void quant_dw_kernel(const float* w0, const float* w1, const float* w2) {
    const int g = blockIdx.y;
    const float* w = g == 0 ? w0 : (g == 1 ? w1 : w2);
    const float scale = fmaxf(g_amaxf[g], 1e-8f) / 127.f;
    int i = blockIdx.x * 256 + threadIdx.x;
    if (i < CH * 9) {
        float q = rintf(w[i] / scale);
        q = fminf(fmaxf(q, -128.f), 127.f);
        g_qwd[g][i] = q * scale;
    }
}
__global__ void quant_pw_kernel(const float* w0, const float* w1, const float* w2) {
    const int g = blockIdx.y;
    const float* w = g == 0 ? w0 : (g == 1 ? w1 : w2);
    const float scale = fmaxf(g_amaxf[3 + g], 1e-8f) / 127.f;
    int i = blockIdx.x * 256 + threadIdx.x;
    if (i < HID * CH) {
        float q = rintf(w[i] / scale);
        q = fminf(fmaxf(q, -128.f), 127.f);
        int o = i / CH, k = i - o * CH;
        g_wpA[g][k >> 6][o * 64 + (k & 63)] = __float2half_rn(q);   // exact integer in fp16
    }
}

// ---------------- fused mainloop with cp.async pipeline ----------------
// smem layout (bytes):
//   0                : float in_s[2][6*34*18]         (2 x 14688)
//   OFF_WD           : float wd[2][NG][64*9]          (2 x NG*2304)
//   OFF_BD           : float bd[2][NG][64]            (2 x NG*256)
//   OFF_A            : half  A[NG][128][72]           (NG*18432, 144B rows)
//   OFF_B            : half  B[NG][128][72]
template<int NG>
__device__ __forceinline__ void mainloop(
    char* sm, u32 sbase,
    const float* __restrict__ src0, const float* __restrict__ srcx,
    const float* __restrict__ bdA, const float* __restrict__ bdB,
    int gate0, int b, int y0, int x0, float acc[2][8][4])
{
    constexpr int NT     = 256 * NG;
    constexpr int IN_SZ  = 14688;
    constexpr int OFF_WD = 2 * IN_SZ;
    constexpr int WD_SZ  = NG * 2304;
    constexpr int OFF_BD = OFF_WD + 2 * WD_SZ;
    constexpr int BD_SZ  = NG * 256;
    constexpr int OFF_A  = OFF_BD + 2 * BD_SZ;
    constexpr int ASZ    = 18432;
    constexpr int OFF_B  = OFF_A + NG * ASZ;

    const int tid = threadIdx.x;
    const int wid = tid >> 5, lane = tid & 31;
    const int g   = (NG == 2) ? (wid >> 3) : 0;
    const int w   = (NG == 2) ? (wid & 7) : wid;
    const int ogB = (w & 3) * 32, pgB = (w >> 2) * 64;

    // dw role: per-gate 256 threads, one vertical 4-px strip per thread
    const int g2   = tid >> 8;          // 0 for q kernel
    const int t2   = tid & 255;
    const int pair = t2 & 7;
    const int cx   = t2 >> 3;           // 0..31

    #pragma unroll
    for (int mi = 0; mi < 2; mi++)
        #pragma unroll
        for (int nj = 0; nj < 8; nj++)
            #pragma unroll
            for (int e = 0; e < 4; e++) acc[mi][nj][e] = 0.f;

    // ldmatrix per-lane offsets (same layout as validated round)
    const u32 aOff = (u32)((lane & 15) * 144 + ((lane >> 4) << 4));
    const u32 bOff = (u32)(((lane & 7) + ((lane >> 4) << 3)) * 144 + (((lane >> 3) & 1) << 4));
    const u32 aBase = sbase + OFF_A + g * ASZ + ogB * 144 + aOff;
    const u32 bBase = sbase + OFF_B + g * ASZ + pgB * 144 + bOff;

    auto issue_halo = [&](int s) {
        const int ibuf = s & 1;
        const int c0 = (s >> 2) * KCM + (s & 3) * KSUB;
        for (int i = tid; i < KSUB * 204; i += NT) {
            int c = i / 204, rem = i - c * 204;
            int yy = rem / 34, xx = rem - yy * 34;
            int gy = y0 - 1 + yy, gx = x0 - 1 + xx;
            bool valid = ((unsigned)gy < IH) && ((unsigned)gx < IW);
            int gyc = valid ? gy : 0, gxc = valid ? gx : 0;
            int gc = c0 + c;
            const float* src = (gc < HID)
                ? src0 + ((b * HID + gc) * IH + gyc) * IW + gxc
                : srcx + ((b * INP + (gc - HID)) * IH + gyc) * IW + gxc;
            cpa4(sbase + ibuf * IN_SZ + ((yy * 34 + xx) * 18 + c) * 4, src, valid);
        }
    };
    auto issue_wd = [&](int cn) {
        const int wb = cn & 1;
        for (int i = tid; i < NG * 576; i += NT) {
            int gg = i / 576, j = i - gg * 576;
            cpa4(sbase + OFF_WD + wb * WD_SZ + gg * 2304 + j * 4,
                 &g_qwd[gate0 + gg][cn * 576 + j], true);
        }
        for (int i = tid; i < NG * 64; i += NT) {
            int gg = i >> 6, j = i & 63;
            cpa4(sbase + OFF_BD + wb * BD_SZ + gg * 256 + j * 4,
                 (gg == 0 ? bdA : bdB) + cn * 64 + j, true);
        }
    };
    auto issue_A = [&](int cn) {
        for (int i = tid; i < NG * 1024; i += NT) {
            int gg = i >> 10, jj = i & 1023;
            int o = jj >> 3, c16 = jj & 7;
            cpa16(sbase + OFF_A + gg * ASZ + o * 144 + c16 * 16,
                  (const int4*)&g_wpA[gate0 + gg][cn][0] + jj);
        }
    };

    // prologue: halo(0) + wd(chunk0) + A(chunk0)
    issue_halo(0); issue_wd(0); issue_A(0); CP_COMMIT();

    for (int s = 0; s < 28; s++) {
        CP_WAIT0();
        __syncthreads();                 // group s arrived; prev dw/MMA done everywhere
        const int nxt = s + 1;
        if (nxt < 28) {
            issue_halo(nxt);
            if ((nxt & 3) == 0) issue_wd(nxt >> 2);   // next chunk weights (double-buffered)
            if ((nxt & 3) == 1) issue_A(nxt >> 2);    // this chunk's A (after prev MMA retired)
            CP_COMMIT();
        }

        // ---- depthwise: vertical 4-px strip, rolling window ----
        const int ibuf = s & 1, sub = s & 3, wb = (s >> 2) & 1;
        const int kk = sub * KSUB + 2 * pair;
        const float* wds = (const float*)(sm + OFF_WD + wb * WD_SZ + g2 * 2304) + kk * 9;
        const float* bds = (const float*)(sm + OFF_BD + wb * BD_SZ + g2 * 256) + kk;
        float w0[9], w1[9];
        #pragma unroll
        for (int j = 0; j < 9; j++) { w0[j] = wds[j]; w1[j] = wds[9 + j]; }
        const float b0 = bds[0], b1 = bds[1];
        const float* ip = (const float*)(sm + ibuf * IN_SZ);

        float a0[4], a1[4];
        #pragma unroll
        for (int o = 0; o < 4; o++) { a0[o] = b0; a1[o] = b1; }
        #pragma unroll
        for (int r = 0; r < 6; r++) {
            const float2 v0 = *(const float2*)(ip + (r * 34 + cx)     * 18 + 2 * pair);
            const float2 v1 = *(const float2*)(ip + (r * 34 + cx + 1) * 18 + 2 * pair);
            const float2 v2 = *(const float2*)(ip + (r * 34 + cx + 2) * 18 + 2 * pair);
            #pragma unroll
            for (int o = 0; o < 4; o++) {
                const int dyw = r - o;
                if (dyw >= 0 && dyw < 3) {
                    a0[o] = fmaf(w0[dyw * 3 + 0], v0.x, a0[o]);
                    a0[o] = fmaf(w0[dyw * 3 + 1], v1.x, a0[o]);
                    a0[o] = fmaf(w0[dyw * 3 + 2], v2.x, a0[o]);
                    a1[o] = fmaf(w1[dyw * 3 + 0], v0.y, a1[o]);
                    a1[o] = fmaf(w1[dyw * 3 + 1], v1.y, a1[o]);
                    a1[o] = fmaf(w1[dyw * 3 + 2], v2.y, a1[o]);
                }
            }
        }
        #pragma unroll
        for (int o = 0; o < 4; o++)
            *(__half2*)(sm + OFF_B + g2 * ASZ + (o * 32 + cx) * 144 + kk * 2) =
                __floats2half2_rn(a0[o], a1[o]);

        if (sub == 3) {
            __syncthreads();             // B tile complete
            #pragma unroll
            for (int ks = 0; ks < 4; ks++) {
                u32 af0[4], af1[4];
                ldm4(af0[0], af0[1], af0[2], af0[3], aBase + ks * 32);
                ldm4(af1[0], af1[1], af1[2], af1[3], aBase + 16 * 144 + ks * 32);
                #pragma unroll
                for (int p = 0; p < 4; p++) {
                    u32 r0, r1, r2, r3;
                    ldm4(r0, r1, r2, r3, bBase + p * 16 * 144 + ks * 32);
                    mma16816(acc[0][2 * p],     af0, r0, r1);
                    mma16816(acc[0][2 * p + 1], af0, r2, r3);
                    mma16816(acc[1][2 * p],     af1, r0, r1);
                    mma16816(acc[1][2 * p + 1], af1, r2, r3);
                }
            }
        }
    }
}

// ---------------- zr kernel ----------------
#define SMEM_ZR 113344
#define SMEM_Q  71360

__global__ void __launch_bounds__(512) zr_kernel(
    const float* __restrict__ h, const float* __restrict__ x,
    const float* __restrict__ bdz, const float* __restrict__ bdr,
    const float* __restrict__ bpz, const float* __restrict__ bpr)
{
    extern __shared__ char sm[];
    const u32 sbase = smem_u32(sm);
    const int b = blockIdx.x >> 6, tt = blockIdx.x & 63;
    const int y0 = (tt >> 2) * 4, x0 = (tt & 3) * 32;

    float acc[2][8][4];
    mainloop<2>(sm, sbase, h, x, bdz, bdr, 0, b, y0, x0, acc);

    const int wid = threadIdx.x >> 5, lane = threadIdx.x & 31;
    const int g = wid >> 3, w = wid & 7;
    const int ogB = (w & 3) * 32, pgB = (w >> 2) * 64;
    const float sc = fmaxf(g_amaxf[3 + g], 1e-8f) / 127.f;
    const float* bp = g ? bpr : bpz;
    const int r4 = lane >> 2, cp = (lane & 3) * 2;

    #pragma unroll
    for (int mi = 0; mi < 2; mi++)
        #pragma unroll
        for (int hh = 0; hh < 2; hh++) {
            const int oc = ogB + mi * 16 + r4 + hh * 8;
            const float bias = bp[oc];
            #pragma unroll
            for (int nj = 0; nj < 8; nj++) {
                const int px = pgB + nj * 8 + cp;
                const int dst = ((b * HID + oc) * IH + y0 + (px >> 5)) * IW + x0 + (px & 31);
                float v0 = acc[mi][nj][hh * 2]     * sc + bias;
                float v1 = acc[mi][nj][hh * 2 + 1] * sc + bias;
                v0 = 1.f / (1.f + __expf(-v0));
                v1 = 1.f / (1.f + __expf(-v1));
                if (g == 0) {
                    *(float2*)(g_Z + dst) = make_float2(v0, v1);
                } else {
                    const float2 hv = *(const float2*)(h + dst);
                    *(float2*)(g_RH + dst) = make_float2(v0 * hv.x, v1 * hv.y);
                }
            }
        }
}

// ---------------- q kernel + final blend ----------------
__global__ void __launch_bounds__(256) q_kernel(
    const float* __restrict__ h, const float* __restrict__ x,
    const float* __restrict__ bdq, const float* __restrict__ bpq,
    float* __restrict__ out)
{
    extern __shared__ char sm[];
    const u32 sbase = smem_u32(sm);
    const int b = blockIdx.x >> 6, tt = blockIdx.x & 63;
    const int y0 = (tt >> 2) * 4, x0 = (tt & 3) * 32;

    float acc[2][8][4];
    mainloop<1>(sm, sbase, g_RH, x, bdq, bdq, 2, b, y0, x0, acc);

    const int wid = threadIdx.x >> 5, lane = threadIdx.x & 31;
    const int ogB = (wid & 3) * 32, pgB = (wid >> 2) * 64;
    const float sc = fmaxf(g_amaxf[5], 1e-8f) / 127.f;
    const int r4 = lane >> 2, cp = (lane & 3) * 2;

    #pragma unroll
    for (int mi = 0; mi < 2; mi++)
        #pragma unroll
        for (int hh = 0; hh < 2; hh++) {
            const int oc = ogB + mi * 16 + r4 + hh * 8;
            const float bias = bpq[oc];
            #pragma unroll
            for (int nj = 0; nj < 8; nj++) {
                const int px = pgB + nj * 8 + cp;
                const int dst = ((b * HID + oc) * IH + y0 + (px >> 5)) * IW + x0 + (px & 31);
                float q0 = tanhf(acc[mi][nj][hh * 2]     * sc + bias);
                float q1 = tanhf(acc[mi][nj][hh * 2 + 1] * sc + bias);
                const float2 zv = *(const float2*)(g_Z + dst);
                const float2 hv = *(const float2*)(h + dst);
                *(float2*)(out + dst) = make_float2(
                    (1.f - zv.x) * hv.x + zv.x * q0,
                    (1.f - zv.y) * hv.y + zv.y * q1);
            }
        }
}

// ---------------- launch ----------------
extern "C" void kernel_launch(void* const* d_in, const int* in_sizes, int n_in,
                              void* d_out, int out_size) {
    const float* h   = (const float*)d_in[0];
    const float* x   = (const float*)d_in[1];
    const float* wdz = (const float*)d_in[2];
    const float* bdz = (const float*)d_in[3];
    const float* wpz = (const float*)d_in[4];
    const float* bpz = (const float*)d_in[5];
    const float* wdr = (const float*)d_in[6];
    const float* bdr = (const float*)d_in[7];
    const float* wpr = (const float*)d_in[8];
    const float* bpr = (const float*)d_in[9];
    const float* wdq = (const float*)d_in[10];
    const float* bdq = (const float*)d_in[11];
    const float* wpq = (const float*)d_in[12];
    const float* bpq = (const float*)d_in[13];
    float* out = (float*)d_out;

    cudaFuncSetAttribute(zr_kernel, cudaFuncAttributeMaxDynamicSharedMemorySize, SMEM_ZR);
    cudaFuncSetAttribute(q_kernel,  cudaFuncAttributeMaxDynamicSharedMemorySize, SMEM_Q);

    amax_all_kernel<<<6, 256>>>(wdz, wdr, wdq, wpz, wpr, wpq);       // launch 0
    dim3 gqd((CH * 9 + 255) / 256, 3);
    quant_dw_kernel<<<gqd, 256>>>(wdz, wdr, wdq);                    // launch 1
    dim3 gqp((HID * CH + 255) / 256, 3);
    quant_pw_kernel<<<gqp, 256>>>(wpz, wpr, wpq);                    // launch 2

    zr_kernel<<<512, 512, SMEM_ZR>>>(h, x, bdz, bdr, bpz, bpr);      // launch 3 (ncu capture slot)
    q_kernel <<<512, 256, SMEM_Q >>>(h, x, bdq, bpq, out);           // launch 4
}

// round 11
// speedup vs baseline: 5.0445x; 1.2359x over previous
#include <cuda_runtime.h>
#include <cuda_fp16.h>

#define HID 128
#define INP 320
#define CH  448
#define BATCH 8
#define IH 64
#define IW 128
#define HW (IH * IW)

#define KCM 64     // K per chunk
#define NKC 7      // 448/64
#define KSUB 16    // dw sub-chunk channels

typedef unsigned int u32;

// ---------------- device scratch ----------------
__device__ float g_qwd[3][CH * 9];                        // dequantized dw weights
__device__ __align__(16) __half g_wpA[3][NKC][128 * KCM]; // pw weights as exact ints in fp16
__device__ float g_Z [BATCH * HID * IH * IW];
__device__ float g_RH[BATCH * HID * IH * IW];
__device__ float g_amaxf[6];

// ---------------- PTX helpers (base sm_103-safe) ----------------
__device__ __forceinline__ u32 smem_u32(const void* p) {
    u32 a;
    asm("{ .reg .u64 t; cvta.to.shared.u64 t, %1; cvt.u32.u64 %0, t; }" : "=r"(a) : "l"(p));
    return a;
}
__device__ __forceinline__ void ldm4(u32& r0, u32& r1, u32& r2, u32& r3, u32 addr) {
    asm volatile("ldmatrix.sync.aligned.m8n8.x4.shared.b16 {%0,%1,%2,%3}, [%4];"
                 : "=r"(r0), "=r"(r1), "=r"(r2), "=r"(r3) : "r"(addr));
}
__device__ __forceinline__ void mma16816(float* d, const u32* a, u32 b0, u32 b1) {
    asm volatile("mma.sync.aligned.m16n8k16.row.col.f32.f16.f16.f32 "
                 "{%0,%1,%2,%3},{%4,%5,%6,%7},{%8,%9},{%0,%1,%2,%3};"
                 : "+f"(d[0]), "+f"(d[1]), "+f"(d[2]), "+f"(d[3])
                 : "r"(a[0]), "r"(a[1]), "r"(a[2]), "r"(a[3]), "r"(b0), "r"(b1));
}
__device__ __forceinline__ void cpa4(u32 dst, const void* src, bool v) {
    asm volatile("cp.async.ca.shared.global [%0], [%1], 4, %2;"
                 :: "r"(dst), "l"(src), "r"(v ? 4u : 0u) : "memory");
}
__device__ __forceinline__ void cpa16(u32 dst, const void* src) {
    asm volatile("cp.async.cg.shared.global [%0], [%1], 16;"
                 :: "r"(dst), "l"(src) : "memory");
}
#define CP_COMMIT() asm volatile("cp.async.commit_group;" ::: "memory")
#define CP_WAIT0()  asm volatile("cp.async.wait_group 0;" ::: "memory")

// ---------------- prep kernels ----------------
__global__ void amax_all_kernel(const float* wdz, const float* wdr, const float* wdq,
                                const float* wpz, const float* wpr, const float* wpq) {
    __shared__ float red[256];
    const float* ws[6] = {wdz, wdr, wdq, wpz, wpr, wpq};
    const int n = blockIdx.x < 3 ? CH * 9 : HID * CH;
    const float* w = ws[blockIdx.x];
    float m = 0.f;
    for (int i = threadIdx.x; i < n; i += 256) m = fmaxf(m, fabsf(w[i]));
    red[threadIdx.x] = m; __syncthreads();
    for (int s = 128; s > 0; s >>= 1) {
        if (threadIdx.x < s) red[threadIdx.x] = fmaxf(red[threadIdx.x], red[threadIdx.x + s]);
        __syncthreads();
    }
    if (threadIdx.x == 0) g_amaxf[blockIdx.x] = red[0];
}
__global__ void quant_dw_kernel(const float* w0, const float* w1, const float* w2) {
    const int g = blockIdx.y;
    const float* w = g == 0 ? w0 : (g == 1 ? w1 : w2);
    const float scale = fmaxf(g_amaxf[g], 1e-8f) / 127.f;
    int i = blockIdx.x * 256 + threadIdx.x;
    if (i < CH * 9) {
        float q = rintf(w[i] / scale);
        q = fminf(fmaxf(q, -128.f), 127.f);
        g_qwd[g][i] = q * scale;
    }
}
__global__ void quant_pw_kernel(const float* w0, const float* w1, const float* w2) {
    const int g = blockIdx.y;
    const float* w = g == 0 ? w0 : (g == 1 ? w1 : w2);
    const float scale = fmaxf(g_amaxf[3 + g], 1e-8f) / 127.f;
    int i = blockIdx.x * 256 + threadIdx.x;
    if (i < HID * CH) {
        float q = rintf(w[i] / scale);
        q = fminf(fmaxf(q, -128.f), 127.f);
        int o = i / CH, k = i - o * CH;
        g_wpA[g][k >> 6][o * 64 + (k & 63)] = __float2half_rn(q);   // exact integer in fp16
    }
}

// ---------------- fused mainloop with cp.async pipeline ----------------
// NT = 512 always. NG=2: warps split across gates (tile 32oc x 64px).
//                  NG=1: all warps one gate (tile 32oc x 32px).
// smem layout (bytes):
//   0       : float in_s[2][6*34*18]       (2 x 14688)
//   OFF_WD  : float wd[2][NG][64*9]
//   OFF_BD  : float bd[2][NG][64]
//   OFF_A   : half  A[NG][128][72]   (144B rows)
//   OFF_B   : half  B[NG][128][72]
template<int NG>
__device__ __forceinline__ void mainloop(
    char* sm, u32 sbase,
    const float* __restrict__ src0, const float* __restrict__ srcx,
    const float* __restrict__ bdA, const float* __restrict__ bdB,
    int gate0, int b, int y0, int x0, float acc[2][8][4])
{
    constexpr int NT     = 512;
    constexpr int IN_SZ  = 14688;
    constexpr int OFF_WD = 2 * IN_SZ;
    constexpr int WD_SZ  = NG * 2304;
    constexpr int OFF_BD = OFF_WD + 2 * WD_SZ;
    constexpr int BD_SZ  = NG * 256;
    constexpr int OFF_A  = OFF_BD + 2 * BD_SZ;
    constexpr int ASZ    = 18432;
    constexpr int OFF_B  = OFF_A + NG * ASZ;
    constexpr int NSLOT  = (KSUB * 204 + NT - 1) / NT;   // 7
    constexpr int NJT    = (NG == 2) ? 8 : 4;            // n-tiles per warp
    constexpr int PT     = NJT / 2;                      // 16-row B ldmatrix groups
    constexpr int NO     = (NG == 2) ? 4 : 2;            // dw output rows per thread

    const int tid = threadIdx.x;
    const int wid = tid >> 5, lane = tid & 31;
    const int g   = (NG == 2) ? (wid >> 3) : 0;
    const int w   = (NG == 2) ? (wid & 7) : wid;
    const int ogB = (w & 3) * 32;
    const int pgB = (NG == 2) ? (w >> 2) * 64 : (w >> 2) * 32;

    // dw role
    const int g2   = (NG == 2) ? (tid >> 8) : 0;
    const int row0 = (NG == 2) ? 0 : (tid >> 8) * 2;
    const int t2   = tid & 255;
    const int pair = t2 & 7;
    const int cx   = t2 >> 3;           // 0..31

    #pragma unroll
    for (int mi = 0; mi < 2; mi++)
        #pragma unroll
        for (int nj = 0; nj < 8; nj++)
            #pragma unroll
            for (int e = 0; e < 4; e++) acc[mi][nj][e] = 0.f;

    // ---- precompute halo slot descriptors (loop-invariant across subs) ----
    u32 hs_sm[NSLOT], hs_off[NSLOT];
    bool hs_ok[NSLOT], hs_val[NSLOT];
    #pragma unroll
    for (int k = 0; k < NSLOT; k++) {
        int i = tid + k * NT;
        hs_ok[k] = i < KSUB * 204;
        int ii = hs_ok[k] ? i : 0;
        int c = ii / 204, rem = ii - c * 204;
        int yy = rem / 34, xx = rem - yy * 34;
        int gy = y0 - 1 + yy, gx = x0 - 1 + xx;
        bool valid = ((unsigned)gy < IH) && ((unsigned)gx < IW);
        hs_val[k] = valid;
        hs_off[k] = (u32)(c * HW + (valid ? gy * IW + gx : 0));
        hs_sm[k]  = (u32)(((yy * 34 + xx) * 18 + c) * 4);
    }
    const float* p0  = src0 + b * HID * HW;
    const float* pxp = srcx + b * INP * HW;

    auto issue_halo = [&](int s) {
        const u32 dstb = sbase + (u32)((s & 1) * IN_SZ);
        const int c0 = (s >> 2) * KCM + (s & 3) * KSUB;
        const float* base = (c0 < HID) ? (p0 + c0 * HW) : (pxp + (c0 - HID) * HW);
        #pragma unroll
        for (int k = 0; k < NSLOT; k++)
            if (hs_ok[k]) cpa4(dstb + hs_sm[k], base + hs_off[k], hs_val[k]);
    };
    auto issue_wd = [&](int cn) {
        const int wb = cn & 1;
        for (int i = tid; i < NG * 576; i += NT) {
            int gg = (NG == 2) ? (i >= 576) : 0;
            int j = i - gg * 576;
            cpa4(sbase + OFF_WD + wb * WD_SZ + gg * 2304 + j * 4,
                 &g_qwd[gate0 + gg][cn * 576 + j], true);
        }
        if (tid < NG * 64) {
            int gg = tid >> 6, j = tid & 63;
            cpa4(sbase + OFF_BD + wb * BD_SZ + gg * 256 + j * 4,
                 (gg == 0 ? bdA : bdB) + cn * 64 + j, true);
        }
    };
    auto issue_A = [&](int cn) {
        for (int i = tid; i < NG * 1024; i += NT) {
            int gg = i >> 10, jj = i & 1023;
            int o = jj >> 3, c16 = jj & 7;
            cpa16(sbase + OFF_A + gg * ASZ + o * 144 + c16 * 16,
                  (const int4*)&g_wpA[gate0 + gg][cn][0] + jj);
        }
    };

    // ldmatrix per-lane offsets
    const u32 aOff = (u32)((lane & 15) * 144 + ((lane >> 4) << 4));
    const u32 bOff = (u32)(((lane & 7) + ((lane >> 4) << 3)) * 144 + (((lane >> 3) & 1) << 4));
    const u32 aBase = sbase + OFF_A + g * ASZ + ogB * 144 + aOff;
    const u32 bBase = sbase + OFF_B + g * ASZ + pgB * 144 + bOff;

    // prologue
    issue_halo(0); issue_wd(0); issue_A(0); CP_COMMIT();

    for (int s = 0; s < 28; s++) {
        CP_WAIT0();
        __syncthreads();
        const int nxt = s + 1;
        if (nxt < 28) {
            issue_halo(nxt);
            if ((nxt & 3) == 0) issue_wd(nxt >> 2);
            if ((nxt & 3) == 1) issue_A(nxt >> 2);
            CP_COMMIT();
        }

        // ---- depthwise: vertical strip, rolling window ----
        const int ibuf = s & 1, sub = s & 3, wb = (s >> 2) & 1;
        const int kk = sub * KSUB + 2 * pair;
        const float* wds = (const float*)(sm + OFF_WD + wb * WD_SZ + g2 * 2304) + kk * 9;
        const float* bds = (const float*)(sm + OFF_BD + wb * BD_SZ + g2 * 256) + kk;
        float w0[9], w1[9];
        #pragma unroll
        for (int j = 0; j < 9; j++) { w0[j] = wds[j]; w1[j] = wds[9 + j]; }
        const float b0 = bds[0], b1 = bds[1];
        const float* ip = (const float*)(sm + ibuf * IN_SZ) + (row0 * 34 + cx) * 18 + 2 * pair;

        float a0[NO], a1[NO];
        #pragma unroll
        for (int o = 0; o < NO; o++) { a0[o] = b0; a1[o] = b1; }
        #pragma unroll
        for (int r = 0; r < NO + 2; r++) {
            const float2 v0 = *(const float2*)(ip + (r * 34 + 0) * 18);
            const float2 v1 = *(const float2*)(ip + (r * 34 + 1) * 18);
            const float2 v2 = *(const float2*)(ip + (r * 34 + 2) * 18);
            #pragma unroll
            for (int o = 0; o < NO; o++) {
                const int dyw = r - o;
                if (dyw >= 0 && dyw < 3) {
                    a0[o] = fmaf(w0[dyw * 3 + 0], v0.x, a0[o]);
                    a0[o] = fmaf(w0[dyw * 3 + 1], v1.x, a0[o]);
                    a0[o] = fmaf(w0[dyw * 3 + 2], v2.x, a0[o]);
                    a1[o] = fmaf(w1[dyw * 3 + 0], v0.y, a1[o]);
                    a1[o] = fmaf(w1[dyw * 3 + 1], v1.y, a1[o]);
                    a1[o] = fmaf(w1[dyw * 3 + 2], v2.y, a1[o]);
                }
            }
        }
        char* bdst = sm + OFF_B + g2 * ASZ + ((row0 * 32 + cx) * 144 + kk * 2);
        #pragma unroll
        for (int o = 0; o < NO; o++)
            *(__half2*)(bdst + o * (32 * 144)) = __floats2half2_rn(a0[o], a1[o]);

        if (sub == 3) {
            __syncthreads();
            #pragma unroll
            for (int ks = 0; ks < 4; ks++) {
                u32 af0[4], af1[4];
                ldm4(af0[0], af0[1], af0[2], af0[3], aBase + ks * 32);
                ldm4(af1[0], af1[1], af1[2], af1[3], aBase + 16 * 144 + ks * 32);
                #pragma unroll
                for (int p = 0; p < PT; p++) {
                    u32 r0, r1, r2, r3;
                    ldm4(r0, r1, r2, r3, bBase + p * 16 * 144 + ks * 32);
                    mma16816(acc[0][2 * p],     af0, r0, r1);
                    mma16816(acc[0][2 * p + 1], af0, r2, r3);
                    mma16816(acc[1][2 * p],     af1, r0, r1);
                    mma16816(acc[1][2 * p + 1], af1, r2, r3);
                }
            }
        }
    }
}

// ---------------- zr kernel ----------------
#define SMEM_ZR 113344
#define SMEM_Q  71360

__global__ void __launch_bounds__(512) zr_kernel(
    const float* __restrict__ h, const float* __restrict__ x,
    const float* __restrict__ bdz, const float* __restrict__ bdr,
    const float* __restrict__ bpz, const float* __restrict__ bpr)
{
    extern __shared__ char sm[];
    const u32 sbase = smem_u32(sm);
    const int b = blockIdx.x >> 6, tt = blockIdx.x & 63;
    const int y0 = (tt >> 2) * 4, x0 = (tt & 3) * 32;

    float acc[2][8][4];
    mainloop<2>(sm, sbase, h, x, bdz, bdr, 0, b, y0, x0, acc);

    const int wid = threadIdx.x >> 5, lane = threadIdx.x & 31;
    const int g = wid >> 3, w = wid & 7;
    const int ogB = (w & 3) * 32, pgB = (w >> 2) * 64;
    const float sc = fmaxf(g_amaxf[3 + g], 1e-8f) / 127.f;
    const float* bp = g ? bpr : bpz;
    const int r4 = lane >> 2, cp = (lane & 3) * 2;

    #pragma unroll
    for (int mi = 0; mi < 2; mi++)
        #pragma unroll
        for (int hh = 0; hh < 2; hh++) {
            const int oc = ogB + mi * 16 + r4 + hh * 8;
            const float bias = bp[oc];
            #pragma unroll
            for (int nj = 0; nj < 8; nj++) {
                const int px = pgB + nj * 8 + cp;
                const int dst = ((b * HID + oc) * IH + y0 + (px >> 5)) * IW + x0 + (px & 31);
                float v0 = acc[mi][nj][hh * 2]     * sc + bias;
                float v1 = acc[mi][nj][hh * 2 + 1] * sc + bias;
                v0 = 1.f / (1.f + __expf(-v0));
                v1 = 1.f / (1.f + __expf(-v1));
                if (g == 0) {
                    *(float2*)(g_Z + dst) = make_float2(v0, v1);
                } else {
                    const float2 hv = *(const float2*)(h + dst);
                    *(float2*)(g_RH + dst) = make_float2(v0 * hv.x, v1 * hv.y);
                }
            }
        }
}

// ---------------- q kernel + final blend (512 threads, 32oc x 32px warp tile) ----------------
__global__ void __launch_bounds__(512) q_kernel(
    const float* __restrict__ h, const float* __restrict__ x,
    const float* __restrict__ bdq, const float* __restrict__ bpq,
    float* __restrict__ out)
{
    extern __shared__ char sm[];
    const u32 sbase = smem_u32(sm);
    const int b = blockIdx.x >> 6, tt = blockIdx.x & 63;
    const int y0 = (tt >> 2) * 4, x0 = (tt & 3) * 32;

    float acc[2][8][4];
    mainloop<1>(sm, sbase, g_RH, x, bdq, bdq, 2, b, y0, x0, acc);

    const int wid = threadIdx.x >> 5, lane = threadIdx.x & 31;
    const int ogB = (wid & 3) * 32, pgB = (wid >> 2) * 32;
    const float sc = fmaxf(g_amaxf[5], 1e-8f) / 127.f;
    const int r4 = lane >> 2, cp = (lane & 3) * 2;

    #pragma unroll
    for (int mi = 0; mi < 2; mi++)
        #pragma unroll
        for (int hh = 0; hh < 2; hh++) {
            const int oc = ogB + mi * 16 + r4 + hh * 8;
            const float bias = bpq[oc];
            #pragma unroll
            for (int nj = 0; nj < 4; nj++) {
                const int px = pgB + nj * 8 + cp;
                const int dst = ((b * HID + oc) * IH + y0 + (px >> 5)) * IW + x0 + (px & 31);
                float q0 = tanhf(acc[mi][nj][hh * 2]     * sc + bias);
                float q1 = tanhf(acc[mi][nj][hh * 2 + 1] * sc + bias);
                const float2 zv = *(const float2*)(g_Z + dst);
                const float2 hv = *(const float2*)(h + dst);
                *(float2*)(out + dst) = make_float2(
                    (1.f - zv.x) * hv.x + zv.x * q0,
                    (1.f - zv.y) * hv.y + zv.y * q1);
            }
        }
}

// ---------------- launch ----------------
extern "C" void kernel_launch(void* const* d_in, const int* in_sizes, int n_in,
                              void* d_out, int out_size) {
    const float* h   = (const float*)d_in[0];
    const float* x   = (const float*)d_in[1];
    const float* wdz = (const float*)d_in[2];
    const float* bdz = (const float*)d_in[3];
    const float* wpz = (const float*)d_in[4];
    const float* bpz = (const float*)d_in[5];
    const float* wdr = (const float*)d_in[6];
    const float* bdr = (const float*)d_in[7];
    const float* wpr = (const float*)d_in[8];
    const float* bpr = (const float*)d_in[9];
    const float* wdq = (const float*)d_in[10];
    const float* bdq = (const float*)d_in[11];
    const float* wpq = (const float*)d_in[12];
    const float* bpq = (const float*)d_in[13];
    float* out = (float*)d_out;

    cudaFuncSetAttribute(zr_kernel, cudaFuncAttributeMaxDynamicSharedMemorySize, SMEM_ZR);
    cudaFuncSetAttribute(q_kernel,  cudaFuncAttributeMaxDynamicSharedMemorySize, SMEM_Q);

    amax_all_kernel<<<6, 256>>>(wdz, wdr, wdq, wpz, wpr, wpq);       // launch 0
    dim3 gqd((CH * 9 + 255) / 256, 3);
    quant_dw_kernel<<<gqd, 256>>>(wdz, wdr, wdq);                    // launch 1
    dim3 gqp((HID * CH + 255) / 256, 3);
    quant_pw_kernel<<<gqp, 256>>>(wpz, wpr, wpq);                    // launch 2

    zr_kernel<<<512, 512, SMEM_ZR>>>(h, x, bdz, bdr, bpz, bpr);      // launch 3 (ncu capture slot)
    q_kernel <<<512, 512, SMEM_Q >>>(h, x, bdq, bpq, out);           // launch 4
}

// round 12
// speedup vs baseline: 6.0815x; 1.2056x over previous
#include <cuda_runtime.h>
#include <cuda_fp16.h>

#define HID 128
#define INP 320
#define CH  448
#define BATCH 8
#define IH 64
#define IW 128
#define HW (IH * IW)

#define KCM 64     // K per chunk
#define NKC 7      // 448/64
#define KSUB 16    // dw sub-chunk channels

typedef unsigned int u32;

// ---------------- device scratch ----------------
__device__ float g_qwd[3][CH * 9];                        // dequantized dw weights
__device__ __align__(16) __half g_wpA[3][NKC][128 * KCM]; // pw weights as exact ints in fp16
__device__ float g_Z [BATCH * HID * IH * IW];
__device__ float g_RH[BATCH * HID * IH * IW];
__device__ float g_amaxf[6];

// ---------------- PTX helpers (base sm_103-safe) ----------------
__device__ __forceinline__ u32 smem_u32(const void* p) {
    u32 a;
    asm("{ .reg .u64 t; cvta.to.shared.u64 t, %1; cvt.u32.u64 %0, t; }" : "=r"(a) : "l"(p));
    return a;
}
__device__ __forceinline__ void ldm4(u32& r0, u32& r1, u32& r2, u32& r3, u32 addr) {
    asm volatile("ldmatrix.sync.aligned.m8n8.x4.shared.b16 {%0,%1,%2,%3}, [%4];"
                 : "=r"(r0), "=r"(r1), "=r"(r2), "=r"(r3) : "r"(addr));
}
__device__ __forceinline__ void mma16816(float* d, const u32* a, u32 b0, u32 b1) {
    asm volatile("mma.sync.aligned.m16n8k16.row.col.f32.f16.f16.f32 "
                 "{%0,%1,%2,%3},{%4,%5,%6,%7},{%8,%9},{%0,%1,%2,%3};"
                 : "+f"(d[0]), "+f"(d[1]), "+f"(d[2]), "+f"(d[3])
                 : "r"(a[0]), "r"(a[1]), "r"(a[2]), "r"(a[3]), "r"(b0), "r"(b1));
}
__device__ __forceinline__ void cpa4(u32 dst, const void* src, bool v) {
    asm volatile("cp.async.ca.shared.global [%0], [%1], 4, %2;"
                 :: "r"(dst), "l"(src), "r"(v ? 4u : 0u) : "memory");
}
__device__ __forceinline__ void cpa16(u32 dst, const void* src, bool v) {
    asm volatile("cp.async.cg.shared.global [%0], [%1], 16, %2;"
                 :: "r"(dst), "l"(src), "r"(v ? 16u : 0u) : "memory");
}
#define CP_COMMIT() asm volatile("cp.async.commit_group;" ::: "memory")
#define CP_WAIT0()  asm volatile("cp.async.wait_group 0;" ::: "memory")

// ---------------- prep kernels ----------------
__global__ void amax_all_kernel(const float* wdz, const float* wdr, const float* wdq,
                                const float* wpz, const float* wpr, const float* wpq) {
    __shared__ float red[256];
    const float* ws[6] = {wdz, wdr, wdq, wpz, wpr, wpq};
    const int n = blockIdx.x < 3 ? CH * 9 : HID * CH;
    const float* w = ws[blockIdx.x];
    float m = 0.f;
    for (int i = threadIdx.x; i < n; i += 256) m = fmaxf(m, fabsf(w[i]));
    red[threadIdx.x] = m; __syncthreads();
    for (int s = 128; s > 0; s >>= 1) {
        if (threadIdx.x < s) red[threadIdx.x] = fmaxf(red[threadIdx.x], red[threadIdx.x + s]);
        __syncthreads();
    }
    if (threadIdx.x == 0) g_amaxf[blockIdx.x] = red[0];
}
__global__ void quant_dw_kernel(const float* w0, const float* w1, const float* w2) {
    const int g = blockIdx.y;
    const float* w = g == 0 ? w0 : (g == 1 ? w1 : w2);
    const float scale = fmaxf(g_amaxf[g], 1e-8f) / 127.f;
    int i = blockIdx.x * 256 + threadIdx.x;
    if (i < CH * 9) {
        float q = rintf(w[i] / scale);
        q = fminf(fmaxf(q, -128.f), 127.f);
        g_qwd[g][i] = q * scale;
    }
}
__global__ void quant_pw_kernel(const float* w0, const float* w1, const float* w2) {
    const int g = blockIdx.y;
    const float* w = g == 0 ? w0 : (g == 1 ? w1 : w2);
    const float scale = fmaxf(g_amaxf[3 + g], 1e-8f) / 127.f;
    int i = blockIdx.x * 256 + threadIdx.x;
    if (i < HID * CH) {
        float q = rintf(w[i] / scale);
        q = fminf(fmaxf(q, -128.f), 127.f);
        int o = i / CH, k = i - o * CH;
        g_wpA[g][k >> 6][o * 64 + (k & 63)] = __float2half_rn(q);   // exact integer in fp16
    }
}

// ---------------- fused mainloop with 16B cp.async pipeline ----------------
// in_s staging: x-contiguous per channel: float [16][6 rows x 44 + 4 pad] (stride 268 floats/ch)
//   row holds gmem x in [x0-4, x0+36), i.e. smem x-idx = (x - x0) + 4.
// smem layout (bytes):
//   0       : float in_s[2][16*268]          (2 x 17152)
//   OFF_WD  : float wd[2][NG][64*9]
//   OFF_BD  : float bd[2][NG][64]
//   OFF_A   : half  A[NG][128][72]   (144B rows)
//   OFF_B   : half  B[NG][128][72]
template<int NG>
__device__ __forceinline__ void mainloop(
    char* sm, u32 sbase,
    const float* __restrict__ src0, const float* __restrict__ srcx,
    const float* __restrict__ bdA, const float* __restrict__ bdB,
    int gate0, int b, int y0, int x0, float acc[2][8][4])
{
    constexpr int NT     = 512;
    constexpr int IN_SZ  = 17152;
    constexpr int OFF_WD = 2 * IN_SZ;
    constexpr int WD_SZ  = NG * 2304;
    constexpr int OFF_BD = OFF_WD + 2 * WD_SZ;
    constexpr int BD_SZ  = NG * 256;
    constexpr int OFF_A  = OFF_BD + 2 * BD_SZ;
    constexpr int ASZ    = 18432;
    constexpr int OFF_B  = OFF_A + NG * ASZ;
    constexpr int NJT    = (NG == 2) ? 8 : 4;
    constexpr int PT     = NJT / 2;
    constexpr int XPT    = (NG == 2) ? 8 : 4;   // x per dw thread
    constexpr int NL4    = (XPT + 8) / 4;       // float4 loads per row

    const int tid = threadIdx.x;
    const int wid = tid >> 5, lane = tid & 31;
    const int g   = (NG == 2) ? (wid >> 3) : 0;
    const int w   = (NG == 2) ? (wid & 7) : wid;
    const int ogB = (w & 3) * 32;
    const int pgB = (NG == 2) ? (w >> 2) * 64 : (w >> 2) * 32;

    // dw role: channel-fastest (conflict-free LDS + contiguous B stores)
    const int g2 = (NG == 2) ? (tid >> 8) : 0;
    const int t2 = (NG == 2) ? (tid & 255) : tid;
    const int cD = t2 & 15;
    const int yD = (NG == 2) ? ((t2 >> 4) & 3) : ((t2 >> 4) & 3);
    const int xgD = (NG == 2) ? (t2 >> 6) : (t2 >> 6);   // 0..3 (8x) | 0..7 (4x)

    #pragma unroll
    for (int mi = 0; mi < 2; mi++)
        #pragma unroll
        for (int nj = 0; nj < 8; nj++)
            #pragma unroll
            for (int e = 0; e < 4; e++) acc[mi][nj][e] = 0.f;

    // ---- halo slot descriptors: 16ch x 6rows x 10 groups = 960 cpa16 per sub ----
    u32 hs_sm[2], hs_off[2];
    bool hs_ok[2], hs_val[2];
    #pragma unroll
    for (int k = 0; k < 2; k++) {
        int i = tid + k * NT;
        hs_ok[k] = i < 960;
        int ii = hs_ok[k] ? i : 0;
        int c = ii / 60, rem = ii - c * 60;
        int row = rem / 10, j = rem - row * 10;
        int gy = y0 - 1 + row, gx = x0 - 4 + 4 * j;
        bool valid = ((unsigned)gy < IH) && ((unsigned)gx < IW) && (gx + 3 < IW);
        hs_val[k] = valid;
        hs_off[k] = (u32)(c * HW + (valid ? gy * IW + gx : 0));
        hs_sm[k]  = (u32)(c * 1072 + row * 176 + j * 16);
    }
    const float* p0  = src0 + b * HID * HW;
    const float* pxp = srcx + b * INP * HW;

    auto issue_halo = [&](int s) {
        const u32 dstb = sbase + (u32)((s & 1) * IN_SZ);
        const int c0 = (s >> 2) * KCM + (s & 3) * KSUB;
        const float* base = (c0 < HID) ? (p0 + c0 * HW) : (pxp + (c0 - HID) * HW);
        #pragma unroll
        for (int k = 0; k < 2; k++)
            if (hs_ok[k]) cpa16(dstb + hs_sm[k], base + hs_off[k], hs_val[k]);
    };
    auto issue_wd = [&](int cn) {
        const int wb = cn & 1;
        for (int i = tid; i < NG * 576; i += NT) {
            int gg = (NG == 2) ? (i >= 576) : 0;
            int j = i - gg * 576;
            cpa4(sbase + OFF_WD + wb * WD_SZ + gg * 2304 + j * 4,
                 &g_qwd[gate0 + gg][cn * 576 + j], true);
        }
        if (tid < NG * 64) {
            int gg = tid >> 6, j = tid & 63;
            cpa4(sbase + OFF_BD + wb * BD_SZ + gg * 256 + j * 4,
                 (gg == 0 ? bdA : bdB) + cn * 64 + j, true);
        }
    };
    auto issue_A = [&](int cn) {
        for (int i = tid; i < NG * 1024; i += NT) {
            int gg = i >> 10, jj = i & 1023;
            int o = jj >> 3, c16 = jj & 7;
            cpa16(sbase + OFF_A + gg * ASZ + o * 144 + c16 * 16,
                  (const int4*)&g_wpA[gate0 + gg][cn][0] + jj, true);
        }
    };

    // ldmatrix per-lane offsets
    const u32 aOff = (u32)((lane & 15) * 144 + ((lane >> 4) << 4));
    const u32 bOff = (u32)(((lane & 7) + ((lane >> 4) << 3)) * 144 + (((lane >> 3) & 1) << 4));
    const u32 aBase = sbase + OFF_A + g * ASZ + ogB * 144 + aOff;
    const u32 bBase = sbase + OFF_B + g * ASZ + pgB * 144 + bOff;

    issue_halo(0); issue_wd(0); issue_A(0); CP_COMMIT();

    for (int s = 0; s < 28; s++) {
        CP_WAIT0();
        __syncthreads();
        const int nxt = s + 1;
        if (nxt < 28) {
            issue_halo(nxt);
            if ((nxt & 3) == 0) issue_wd(nxt >> 2);
            if ((nxt & 3) == 1) issue_A(nxt >> 2);
            CP_COMMIT();
        }

        // ---- depthwise: 1 channel x XPT x x 1 y per thread ----
        const int ibuf = s & 1, sub = s & 3, wb = (s >> 2) & 1;
        const int kk = sub * KSUB + cD;
        const float* wds = (const float*)(sm + OFF_WD + wb * WD_SZ + g2 * 2304) + kk * 9;
        float wv[9];
        #pragma unroll
        for (int j = 0; j < 9; j++) wv[j] = wds[j];
        const float bv = ((const float*)(sm + OFF_BD + wb * BD_SZ + g2 * 256))[kk];
        const float* ipc = (const float*)(sm + ibuf * IN_SZ) + cD * 268 + yD * 44 + XPT * xgD;

        float ad[XPT];
        #pragma unroll
        for (int i = 0; i < XPT; i++) ad[i] = bv;
        #pragma unroll
        for (int r = 0; r < 3; r++) {
            float f[NL4 * 4];
            #pragma unroll
            for (int l = 0; l < NL4; l++)
                *(float4*)&f[l * 4] = *(const float4*)(ipc + r * 44 + l * 4);
            #pragma unroll
            for (int i = 0; i < XPT; i++) {
                ad[i] = fmaf(wv[r * 3 + 0], f[i + 3], ad[i]);
                ad[i] = fmaf(wv[r * 3 + 1], f[i + 4], ad[i]);
                ad[i] = fmaf(wv[r * 3 + 2], f[i + 5], ad[i]);
            }
        }
        char* bdst = sm + OFF_B + g2 * ASZ + ((yD * 32 + XPT * xgD) * 144 + kk * 2);
        #pragma unroll
        for (int i = 0; i < XPT; i++)
            *(__half*)(bdst + i * 144) = __float2half_rn(ad[i]);

        if (sub == 3) {
            __syncthreads();
            #pragma unroll
            for (int ks = 0; ks < 4; ks++) {
                u32 af0[4], af1[4];
                ldm4(af0[0], af0[1], af0[2], af0[3], aBase + ks * 32);
                ldm4(af1[0], af1[1], af1[2], af1[3], aBase + 16 * 144 + ks * 32);
                #pragma unroll
                for (int p = 0; p < PT; p++) {
                    u32 r0, r1, r2, r3;
                    ldm4(r0, r1, r2, r3, bBase + p * 16 * 144 + ks * 32);
                    mma16816(acc[0][2 * p],     af0, r0, r1);
                    mma16816(acc[0][2 * p + 1], af0, r2, r3);
                    mma16816(acc[1][2 * p],     af1, r0, r1);
                    mma16816(acc[1][2 * p + 1], af1, r2, r3);
                }
            }
        }
    }
}

// ---------------- zr kernel ----------------
#define SMEM_ZR 118272
#define SMEM_Q  76288

__global__ void __launch_bounds__(512) zr_kernel(
    const float* __restrict__ h, const float* __restrict__ x,
    const float* __restrict__ bdz, const float* __restrict__ bdr,
    const float* __restrict__ bpz, const float* __restrict__ bpr)
{
    extern __shared__ char sm[];
    const u32 sbase = smem_u32(sm);
    const int b = blockIdx.x >> 6, tt = blockIdx.x & 63;
    const int y0 = (tt >> 2) * 4, x0 = (tt & 3) * 32;

    float acc[2][8][4];
    mainloop<2>(sm, sbase, h, x, bdz, bdr, 0, b, y0, x0, acc);

    const int wid = threadIdx.x >> 5, lane = threadIdx.x & 31;
    const int g = wid >> 3, w = wid & 7;
    const int ogB = (w & 3) * 32, pgB = (w >> 2) * 64;
    const float sc = fmaxf(g_amaxf[3 + g], 1e-8f) / 127.f;
    const float* bp = g ? bpr : bpz;
    const int r4 = lane >> 2, cp = (lane & 3) * 2;

    #pragma unroll
    for (int mi = 0; mi < 2; mi++)
        #pragma unroll
        for (int hh = 0; hh < 2; hh++) {
            const int oc = ogB + mi * 16 + r4 + hh * 8;
            const float bias = bp[oc];
            #pragma unroll
            for (int nj = 0; nj < 8; nj++) {
                const int px = pgB + nj * 8 + cp;
                const int dst = ((b * HID + oc) * IH + y0 + (px >> 5)) * IW + x0 + (px & 31);
                float v0 = acc[mi][nj][hh * 2]     * sc + bias;
                float v1 = acc[mi][nj][hh * 2 + 1] * sc + bias;
                v0 = 1.f / (1.f + __expf(-v0));
                v1 = 1.f / (1.f + __expf(-v1));
                if (g == 0) {
                    *(float2*)(g_Z + dst) = make_float2(v0, v1);
                } else {
                    const float2 hv = *(const float2*)(h + dst);
                    *(float2*)(g_RH + dst) = make_float2(v0 * hv.x, v1 * hv.y);
                }
            }
        }
}

// ---------------- q kernel + final blend ----------------
__global__ void __launch_bounds__(512) q_kernel(
    const float* __restrict__ h, const float* __restrict__ x,
    const float* __restrict__ bdq, const float* __restrict__ bpq,
    float* __restrict__ out)
{
    extern __shared__ char sm[];
    const u32 sbase = smem_u32(sm);
    const int b = blockIdx.x >> 6, tt = blockIdx.x & 63;
    const int y0 = (tt >> 2) * 4, x0 = (tt & 3) * 32;

    float acc[2][8][4];
    mainloop<1>(sm, sbase, g_RH, x, bdq, bdq, 2, b, y0, x0, acc);

    const int wid = threadIdx.x >> 5, lane = threadIdx.x & 31;
    const int ogB = (wid & 3) * 32, pgB = (wid >> 2) * 32;
    const float sc = fmaxf(g_amaxf[5], 1e-8f) / 127.f;
    const int r4 = lane >> 2, cp = (lane & 3) * 2;

    #pragma unroll
    for (int mi = 0; mi < 2; mi++)
        #pragma unroll
        for (int hh = 0; hh < 2; hh++) {
            const int oc = ogB + mi * 16 + r4 + hh * 8;
            const float bias = bpq[oc];
            #pragma unroll
            for (int nj = 0; nj < 4; nj++) {
                const int px = pgB + nj * 8 + cp;
                const int dst = ((b * HID + oc) * IH + y0 + (px >> 5)) * IW + x0 + (px & 31);
                float q0 = tanhf(acc[mi][nj][hh * 2]     * sc + bias);
                float q1 = tanhf(acc[mi][nj][hh * 2 + 1] * sc + bias);
                const float2 zv = *(const float2*)(g_Z + dst);
                const float2 hv = *(const float2*)(h + dst);
                *(float2*)(out + dst) = make_float2(
                    (1.f - zv.x) * hv.x + zv.x * q0,
                    (1.f - zv.y) * hv.y + zv.y * q1);
            }
        }
}

// ---------------- launch ----------------
extern "C" void kernel_launch(void* const* d_in, const int* in_sizes, int n_in,
                              void* d_out, int out_size) {
    const float* h   = (const float*)d_in[0];
    const float* x   = (const float*)d_in[1];
    const float* wdz = (const float*)d_in[2];
    const float* bdz = (const float*)d_in[3];
    const float* wpz = (const float*)d_in[4];
    const float* bpz = (const float*)d_in[5];
    const float* wdr = (const float*)d_in[6];
    const float* bdr = (const float*)d_in[7];
    const float* wpr = (const float*)d_in[8];
    const float* bpr = (const float*)d_in[9];
    const float* wdq = (const float*)d_in[10];
    const float* bdq = (const float*)d_in[11];
    const float* wpq = (const float*)d_in[12];
    const float* bpq = (const float*)d_in[13];
    float* out = (float*)d_out;

    cudaFuncSetAttribute(zr_kernel, cudaFuncAttributeMaxDynamicSharedMemorySize, SMEM_ZR);
    cudaFuncSetAttribute(q_kernel,  cudaFuncAttributeMaxDynamicSharedMemorySize, SMEM_Q);

    amax_all_kernel<<<6, 256>>>(wdz, wdr, wdq, wpz, wpr, wpq);       // launch 0
    dim3 gqd((CH * 9 + 255) / 256, 3);
    quant_dw_kernel<<<gqd, 256>>>(wdz, wdr, wdq);                    // launch 1
    dim3 gqp((HID * CH + 255) / 256, 3);
    quant_pw_kernel<<<gqp, 256>>>(wpz, wpr, wpq);                    // launch 2

    zr_kernel<<<512, 512, SMEM_ZR>>>(h, x, bdz, bdr, bpz, bpr);      // launch 3 (ncu capture slot)
    q_kernel <<<512, 512, SMEM_Q >>>(h, x, bdq, bpq, out);           // launch 4
}

// round 13
// speedup vs baseline: 6.6840x; 1.0991x over previous
#include <cuda_runtime.h>
#include <cuda_fp16.h>

#define HID 128
#define INP 320
#define CH  448
#define BATCH 8
#define IH 64
#define IW 128
#define HW (IH * IW)

#define KCM 64     // K per chunk
#define NKC 7      // 448/64
#define KSUB 16    // dw sub-chunk channels

typedef unsigned int u32;

// ---------------- device scratch ----------------
__device__ float g_qwd[3][CH * 9];                        // dequantized dw weights
__device__ __align__(16) __half g_wpA[3][NKC][128 * KCM]; // pw weights as exact ints in fp16
__device__ float g_Z [BATCH * HID * IH * IW];
__device__ float g_RH[BATCH * HID * IH * IW];
__device__ float g_amaxf[6];

// ---------------- PTX helpers (base sm_103-safe) ----------------
__device__ __forceinline__ u32 smem_u32(const void* p) {
    u32 a;
    asm("{ .reg .u64 t; cvta.to.shared.u64 t, %1; cvt.u32.u64 %0, t; }" : "=r"(a) : "l"(p));
    return a;
}
__device__ __forceinline__ void ldm4(u32& r0, u32& r1, u32& r2, u32& r3, u32 addr) {
    asm volatile("ldmatrix.sync.aligned.m8n8.x4.shared.b16 {%0,%1,%2,%3}, [%4];"
                 : "=r"(r0), "=r"(r1), "=r"(r2), "=r"(r3) : "r"(addr));
}
__device__ __forceinline__ void mma16816(float* d, const u32* a, u32 b0, u32 b1) {
    asm volatile("mma.sync.aligned.m16n8k16.row.col.f32.f16.f16.f32 "
                 "{%0,%1,%2,%3},{%4,%5,%6,%7},{%8,%9},{%0,%1,%2,%3};"
                 : "+f"(d[0]), "+f"(d[1]), "+f"(d[2]), "+f"(d[3])
                 : "r"(a[0]), "r"(a[1]), "r"(a[2]), "r"(a[3]), "r"(b0), "r"(b1));
}
__device__ __forceinline__ void cpa4(u32 dst, const void* src, bool v) {
    asm volatile("cp.async.ca.shared.global [%0], [%1], 4, %2;"
                 :: "r"(dst), "l"(src), "r"(v ? 4u : 0u) : "memory");
}
__device__ __forceinline__ void cpa16(u32 dst, const void* src, bool v) {
    asm volatile("cp.async.cg.shared.global [%0], [%1], 16, %2;"
                 :: "r"(dst), "l"(src), "r"(v ? 16u : 0u) : "memory");
}
#define CP_COMMIT() asm volatile("cp.async.commit_group;" ::: "memory")
#define CP_WAIT1()  asm volatile("cp.async.wait_group 1;" ::: "memory")

// ---------------- prep kernels ----------------
__global__ void amax_all_kernel(const float* wdz, const float* wdr, const float* wdq,
                                const float* wpz, const float* wpr, const float* wpq) {
    __shared__ float red[256];
    const float* ws[6] = {wdz, wdr, wdq, wpz, wpr, wpq};
    const int n = blockIdx.x < 3 ? CH * 9 : HID * CH;
    const float* w = ws[blockIdx.x];
    float m = 0.f;
    for (int i = threadIdx.x; i < n; i += 256) m = fmaxf(m, fabsf(w[i]));
    red[threadIdx.x] = m; __syncthreads();
    for (int s = 128; s > 0; s >>= 1) {
        if (threadIdx.x < s) red[threadIdx.x] = fmaxf(red[threadIdx.x], red[threadIdx.x + s]);
        __syncthreads();
    }
    if (threadIdx.x == 0) g_amaxf[blockIdx.x] = red[0];
}
__global__ void quant_dw_kernel(const float* w0, const float* w1, const float* w2) {
    const int g = blockIdx.y;
    const float* w = g == 0 ? w0 : (g == 1 ? w1 : w2);
    const float scale = fmaxf(g_amaxf[g], 1e-8f) / 127.f;
    int i = blockIdx.x * 256 + threadIdx.x;
    if (i < CH * 9) {
        float q = rintf(w[i] / scale);
        q = fminf(fmaxf(q, -128.f), 127.f);
        g_qwd[g][i] = q * scale;
    }
}
__global__ void quant_pw_kernel(const float* w0, const float* w1, const float* w2) {
    const int g = blockIdx.y;
    const float* w = g == 0 ? w0 : (g == 1 ? w1 : w2);
    const float scale = fmaxf(g_amaxf[3 + g], 1e-8f) / 127.f;
    int i = blockIdx.x * 256 + threadIdx.x;
    if (i < HID * CH) {
        float q = rintf(w[i] / scale);
        q = fminf(fmaxf(q, -128.f), 127.f);
        int o = i / CH, k = i - o * CH;
        g_wpA[g][k >> 6][o * 64 + (k & 63)] = __float2half_rn(q);   // exact integer in fp16
    }
}

// ---------------- fused mainloop, prefetch-distance-2 cp.async pipeline ----------------
// smem layout (bytes):
//   0       : float in_s[3][16*268]           (3 x 17152) — triple-buffered halo
//   OFF_WD  : float wd[2][NG][64*9]
//   OFF_BD  : float bd[2][NG][64]
//   OFF_A   : half  A[2][NG][128][72]  (144B rows) — double-buffered per chunk parity
//   OFF_B   : half  B[NG][128][72]
template<int NG>
__device__ __forceinline__ void mainloop(
    char* sm, u32 sbase,
    const float* __restrict__ src0, const float* __restrict__ srcx,
    const float* __restrict__ bdA, const float* __restrict__ bdB,
    int gate0, int b, int y0, int x0, float acc[2][8][4])
{
    constexpr int NT     = 512;
    constexpr int IN_SZ  = 17152;
    constexpr int OFF_WD = 3 * IN_SZ;
    constexpr int WD_SZ  = NG * 2304;
    constexpr int OFF_BD = OFF_WD + 2 * WD_SZ;
    constexpr int BD_SZ  = NG * 256;
    constexpr int OFF_A  = OFF_BD + 2 * BD_SZ;
    constexpr int ASZ    = 18432;
    constexpr int OFF_B  = OFF_A + 2 * NG * ASZ;
    constexpr int NJT    = (NG == 2) ? 8 : 4;
    constexpr int PT     = NJT / 2;
    constexpr int XPT    = (NG == 2) ? 8 : 4;   // x per dw thread
    constexpr int NL4    = (XPT + 8) / 4;       // float4 loads per row

    const int tid = threadIdx.x;
    const int wid = tid >> 5, lane = tid & 31;
    const int g   = (NG == 2) ? (wid >> 3) : 0;
    const int w   = (NG == 2) ? (wid & 7) : wid;
    const int ogB = (w & 3) * 32;
    const int pgB = (NG == 2) ? (w >> 2) * 64 : (w >> 2) * 32;

    // dw role: channel-fastest (conflict-free LDS + contiguous B stores)
    const int g2 = (NG == 2) ? (tid >> 8) : 0;
    const int t2 = (NG == 2) ? (tid & 255) : tid;
    const int cD = t2 & 15;
    const int yD = (t2 >> 4) & 3;
    const int xgD = t2 >> 6;

    #pragma unroll
    for (int mi = 0; mi < 2; mi++)
        #pragma unroll
        for (int nj = 0; nj < 8; nj++)
            #pragma unroll
            for (int e = 0; e < 4; e++) acc[mi][nj][e] = 0.f;

    // ---- halo slot descriptors: 16ch x 6rows x 10 groups = 960 cpa16 per sub ----
    u32 hs_sm[2], hs_off[2];
    bool hs_ok[2], hs_val[2];
    #pragma unroll
    for (int k = 0; k < 2; k++) {
        int i = tid + k * NT;
        hs_ok[k] = i < 960;
        int ii = hs_ok[k] ? i : 0;
        int c = ii / 60, rem = ii - c * 60;
        int row = rem / 10, j = rem - row * 10;
        int gy = y0 - 1 + row, gx = x0 - 4 + 4 * j;
        bool valid = ((unsigned)gy < IH) && ((unsigned)gx < IW) && (gx + 3 < IW);
        hs_val[k] = valid;
        hs_off[k] = (u32)(c * HW + (valid ? gy * IW + gx : 0));
        hs_sm[k]  = (u32)(c * 1072 + row * 176 + j * 16);
    }
    const float* p0  = src0 + b * HID * HW;
    const float* pxp = srcx + b * INP * HW;

    auto issue_halo = [&](int s, int buf) {
        const u32 dstb = sbase + (u32)(buf * IN_SZ);
        const int c0 = (s >> 2) * KCM + (s & 3) * KSUB;
        const float* base = (c0 < HID) ? (p0 + c0 * HW) : (pxp + (c0 - HID) * HW);
        #pragma unroll
        for (int k = 0; k < 2; k++)
            if (hs_ok[k]) cpa16(dstb + hs_sm[k], base + hs_off[k], hs_val[k]);
    };
    auto issue_wd = [&](int cn) {
        const int wb = cn & 1;
        for (int i = tid; i < NG * 576; i += NT) {
            int gg = (NG == 2) ? (i >= 576) : 0;
            int j = i - gg * 576;
            cpa4(sbase + OFF_WD + wb * WD_SZ + gg * 2304 + j * 4,
                 &g_qwd[gate0 + gg][cn * 576 + j], true);
        }
        if (tid < NG * 64) {
            int gg = tid >> 6, j = tid & 63;
            cpa4(sbase + OFF_BD + wb * BD_SZ + gg * 256 + j * 4,
                 (gg == 0 ? bdA : bdB) + cn * 64 + j, true);
        }
    };
    auto issue_A = [&](int cn) {
        const int ab = cn & 1;
        for (int i = tid; i < NG * 1024; i += NT) {
            int gg = i >> 10, jj = i & 1023;
            int o = jj >> 3, c16 = jj & 7;
            cpa16(sbase + OFF_A + (ab * NG + gg) * ASZ + o * 144 + c16 * 16,
                  (const int4*)&g_wpA[gate0 + gg][cn][0] + jj, true);
        }
    };

    // ldmatrix per-lane offsets
    const u32 aOff = (u32)((lane & 15) * 144 + ((lane >> 4) << 4));
    const u32 bOff = (u32)(((lane & 7) + ((lane >> 4) << 3)) * 144 + (((lane >> 3) & 1) << 4));
    const u32 bBase = sbase + OFF_B + g * ASZ + pgB * 144 + bOff;

    // prologue: distance-2 prefetch (group index == target stage)
    issue_halo(0, 0); issue_wd(0); CP_COMMIT();      // target 0
    issue_halo(1, 1); issue_A(0);  CP_COMMIT();      // target 1

    int ibuf = 0;       // = s % 3
    for (int s = 0; s < 28; s++) {
        CP_WAIT1();                    // groups <= s complete; s+1 still flying
        __syncthreads();
        const int t = s + 2;
        if (t < 28) {
            int tb = ibuf + 2; if (tb >= 3) tb -= 3;   // (s+2) % 3
            issue_halo(t, tb);
            if ((t & 3) == 0) issue_wd(t >> 2);
            if ((t & 3) == 1) issue_A(t >> 2);
        }
        CP_COMMIT();

        // ---- depthwise: 1 channel x XPT x x 1 y per thread ----
        const int sub = s & 3, wb = (s >> 2) & 1;
        const int kk = sub * KSUB + cD;
        const float* wds = (const float*)(sm + OFF_WD + wb * WD_SZ + g2 * 2304) + kk * 9;
        float wv[9];
        #pragma unroll
        for (int j = 0; j < 9; j++) wv[j] = wds[j];
        const float bv = ((const float*)(sm + OFF_BD + wb * BD_SZ + g2 * 256))[kk];
        const float* ipc = (const float*)(sm + ibuf * IN_SZ) + cD * 268 + yD * 44 + XPT * xgD;

        float ad[XPT];
        #pragma unroll
        for (int i = 0; i < XPT; i++) ad[i] = bv;
        #pragma unroll
        for (int r = 0; r < 3; r++) {
            float f[NL4 * 4];
            #pragma unroll
            for (int l = 0; l < NL4; l++)
                *(float4*)&f[l * 4] = *(const float4*)(ipc + r * 44 + l * 4);
            #pragma unroll
            for (int i = 0; i < XPT; i++) {
                ad[i] = fmaf(wv[r * 3 + 0], f[i + 3], ad[i]);
                ad[i] = fmaf(wv[r * 3 + 1], f[i + 4], ad[i]);
                ad[i] = fmaf(wv[r * 3 + 2], f[i + 5], ad[i]);
            }
        }
        char* bdst = sm + OFF_B + g2 * ASZ + ((yD * 32 + XPT * xgD) * 144 + kk * 2);
        #pragma unroll
        for (int i = 0; i < XPT; i++)
            *(__half*)(bdst + i * 144) = __float2half_rn(ad[i]);

        if (sub == 3) {
            __syncthreads();
            const int kc = s >> 2;
            const u32 aBase = sbase + OFF_A + ((u32)((kc & 1) * NG + g)) * ASZ + ogB * 144 + aOff;
            #pragma unroll
            for (int ks = 0; ks < 4; ks++) {
                u32 af0[4], af1[4];
                ldm4(af0[0], af0[1], af0[2], af0[3], aBase + ks * 32);
                ldm4(af1[0], af1[1], af1[2], af1[3], aBase + 16 * 144 + ks * 32);
                #pragma unroll
                for (int p = 0; p < PT; p++) {
                    u32 r0, r1, r2, r3;
                    ldm4(r0, r1, r2, r3, bBase + p * 16 * 144 + ks * 32);
                    mma16816(acc[0][2 * p],     af0, r0, r1);
                    mma16816(acc[0][2 * p + 1], af0, r2, r3);
                    mma16816(acc[1][2 * p],     af1, r0, r1);
                    mma16816(acc[1][2 * p + 1], af1, r2, r3);
                }
            }
        }
        if (++ibuf == 3) ibuf = 0;
    }
}

// ---------------- zr kernel ----------------
#define SMEM_ZR (3*17152 + 2*2*2304 + 2*2*256 + 2*2*18432 + 2*18432)   // 172288
#define SMEM_Q  (3*17152 + 2*1*2304 + 2*1*256 + 2*1*18432 + 1*18432)   // 111872

__global__ void __launch_bounds__(512) zr_kernel(
    const float* __restrict__ h, const float* __restrict__ x,
    const float* __restrict__ bdz, const float* __restrict__ bdr,
    const float* __restrict__ bpz, const float* __restrict__ bpr)
{
    extern __shared__ char sm[];
    const u32 sbase = smem_u32(sm);
    const int b = blockIdx.x >> 6, tt = blockIdx.x & 63;
    const int y0 = (tt >> 2) * 4, x0 = (tt & 3) * 32;

    float acc[2][8][4];
    mainloop<2>(sm, sbase, h, x, bdz, bdr, 0, b, y0, x0, acc);

    const int wid = threadIdx.x >> 5, lane = threadIdx.x & 31;
    const int g = wid >> 3, w = wid & 7;
    const int ogB = (w & 3) * 32, pgB = (w >> 2) * 64;
    const float sc = fmaxf(g_amaxf[3 + g], 1e-8f) / 127.f;
    const float* bp = g ? bpr : bpz;
    const int r4 = lane >> 2, cp = (lane & 3) * 2;

    #pragma unroll
    for (int mi = 0; mi < 2; mi++)
        #pragma unroll
        for (int hh = 0; hh < 2; hh++) {
            const int oc = ogB + mi * 16 + r4 + hh * 8;
            const float bias = bp[oc];
            #pragma unroll
            for (int nj = 0; nj < 8; nj++) {
                const int px = pgB + nj * 8 + cp;
                const int dst = ((b * HID + oc) * IH + y0 + (px >> 5)) * IW + x0 + (px & 31);
                float v0 = acc[mi][nj][hh * 2]     * sc + bias;
                float v1 = acc[mi][nj][hh * 2 + 1] * sc + bias;
                v0 = 1.f / (1.f + __expf(-v0));
                v1 = 1.f / (1.f + __expf(-v1));
                if (g == 0) {
                    *(float2*)(g_Z + dst) = make_float2(v0, v1);
                } else {
                    const float2 hv = *(const float2*)(h + dst);
                    *(float2*)(g_RH + dst) = make_float2(v0 * hv.x, v1 * hv.y);
                }
            }
        }
}

// ---------------- q kernel + final blend ----------------
__global__ void __launch_bounds__(512) q_kernel(
    const float* __restrict__ h, const float* __restrict__ x,
    const float* __restrict__ bdq, const float* __restrict__ bpq,
    float* __restrict__ out)
{
    extern __shared__ char sm[];
    const u32 sbase = smem_u32(sm);
    const int b = blockIdx.x >> 6, tt = blockIdx.x & 63;
    const int y0 = (tt >> 2) * 4, x0 = (tt & 3) * 32;

    float acc[2][8][4];
    mainloop<1>(sm, sbase, g_RH, x, bdq, bdq, 2, b, y0, x0, acc);

    const int wid = threadIdx.x >> 5, lane = threadIdx.x & 31;
    const int ogB = (wid & 3) * 32, pgB = (wid >> 2) * 32;
    const float sc = fmaxf(g_amaxf[5], 1e-8f) / 127.f;
    const int r4 = lane >> 2, cp = (lane & 3) * 2;

    #pragma unroll
    for (int mi = 0; mi < 2; mi++)
        #pragma unroll
        for (int hh = 0; hh < 2; hh++) {
            const int oc = ogB + mi * 16 + r4 + hh * 8;
            const float bias = bpq[oc];
            #pragma unroll
            for (int nj = 0; nj < 4; nj++) {
                const int px = pgB + nj * 8 + cp;
                const int dst = ((b * HID + oc) * IH + y0 + (px >> 5)) * IW + x0 + (px & 31);
                float q0 = tanhf(acc[mi][nj][hh * 2]     * sc + bias);
                float q1 = tanhf(acc[mi][nj][hh * 2 + 1] * sc + bias);
                const float2 zv = *(const float2*)(g_Z + dst);
                const float2 hv = *(const float2*)(h + dst);
                *(float2*)(out + dst) = make_float2(
                    (1.f - zv.x) * hv.x + zv.x * q0,
                    (1.f - zv.y) * hv.y + zv.y * q1);
            }
        }
}

// ---------------- launch ----------------
extern "C" void kernel_launch(void* const* d_in, const int* in_sizes, int n_in,
                              void* d_out, int out_size) {
    const float* h   = (const float*)d_in[0];
    const float* x   = (const float*)d_in[1];
    const float* wdz = (const float*)d_in[2];
    const float* bdz = (const float*)d_in[3];
    const float* wpz = (const float*)d_in[4];
    const float* bpz = (const float*)d_in[5];
    const float* wdr = (const float*)d_in[6];
    const float* bdr = (const float*)d_in[7];
    const float* wpr = (const float*)d_in[8];
    const float* bpr = (const float*)d_in[9];
    const float* wdq = (const float*)d_in[10];
    const float* bdq = (const float*)d_in[11];
    const float* wpq = (const float*)d_in[12];
    const float* bpq = (const float*)d_in[13];
    float* out = (float*)d_out;

    cudaFuncSetAttribute(zr_kernel, cudaFuncAttributeMaxDynamicSharedMemorySize, SMEM_ZR);
    cudaFuncSetAttribute(q_kernel,  cudaFuncAttributeMaxDynamicSharedMemorySize, SMEM_Q);

    amax_all_kernel<<<6, 256>>>(wdz, wdr, wdq, wpz, wpr, wpq);       // launch 0
    dim3 gqd((CH * 9 + 255) / 256, 3);
    quant_dw_kernel<<<gqd, 256>>>(wdz, wdr, wdq);                    // launch 1
    dim3 gqp((HID * CH + 255) / 256, 3);
    quant_pw_kernel<<<gqp, 256>>>(wpz, wpr, wpq);                    // launch 2

    zr_kernel<<<512, 512, SMEM_ZR>>>(h, x, bdz, bdr, bpz, bpr);      // launch 3 (ncu capture slot)
    q_kernel <<<512, 512, SMEM_Q >>>(h, x, bdq, bpq, out);           // launch 4
}